// round 6
// baseline (speedup 1.0000x reference)
#include <cuda_runtime.h>
#include <cuda_fp16.h>
#include <cstdint>
#include <math_constants.h>

// ---------------------------------------------------------------------------
#define BB   8
#define DD   256
#define TT   2048
#define NE   8192
#define MTOK (BB * TT)        // 16384
#define BDT  (BB * DD * TT)   // 4194304

#define MT    128             // tokens per tile
#define NTILE 128             // codes per N-tile
#define NBLK  8               // n-blocks per token tile (1024 codes each)
#define NUNITS (MTOK / MT * NBLK)   // 1024 work units
#define NCTA  148
#define KCH   64

#define GATHER_BLOCKS 2048
#define LO_SCALE   4096.0f
#define LO_UNSCALE 2.44140625e-4f    // 2^-12

// ---------------------------------------------------------------------------
__device__ float  g_A[MTOK];
__device__ float  g_Bsq[NE];
__device__ int    g_idx[MTOK];
__device__ double g_part[GATHER_BLOCKS];
__device__ __half g_Zh[(size_t)MTOK * DD];
__device__ __half g_Zl[(size_t)MTOK * DD];
__device__ __half g_Eh[(size_t)NE * DD];
__device__ __half g_El[(size_t)NE * DD];
__device__ float  g_pd[(size_t)MTOK * NBLK * 4];
__device__ int    g_pi[(size_t)MTOK * NBLK * 4];

// ---------------------------------------------------------------------------
__device__ __forceinline__ uint32_t smem_u32(const void* p) {
    uint32_t a;
    asm("{ .reg .u64 t; cvta.to.shared.u64 t, %1; cvt.u32.u64 %0, t; }"
        : "=r"(a) : "l"(p));
    return a;
}
__device__ __forceinline__ void cp16(uint32_t dst, const void* src) {
    asm volatile("cp.async.cg.shared.global [%0], [%1], 16;" :: "r"(dst), "l"(src));
}
__device__ __forceinline__ void cp_commit() {
    asm volatile("cp.async.commit_group;" ::: "memory");
}
template <int N>
__device__ __forceinline__ void cp_wait() {
    asm volatile("cp.async.wait_group %0;" :: "n"(N) : "memory");
}
__device__ __forceinline__ void ldsm4(uint32_t* r, uint32_t a) {
    asm volatile("ldmatrix.sync.aligned.m8n8.x4.shared.b16 {%0,%1,%2,%3}, [%4];"
        : "=r"(r[0]), "=r"(r[1]), "=r"(r[2]), "=r"(r[3]) : "r"(a));
}
__device__ __forceinline__ void mma16816(float* d, const uint32_t* a, const uint32_t* b) {
    asm volatile("mma.sync.aligned.m16n8k16.row.col.f32.f16.f16.f32 "
        "{%0,%1,%2,%3}, {%4,%5,%6,%7}, {%8,%9}, {%0,%1,%2,%3};"
        : "+f"(d[0]), "+f"(d[1]), "+f"(d[2]), "+f"(d[3])
        : "r"(a[0]), "r"(a[1]), "r"(a[2]), "r"(a[3]), "r"(b[0]), "r"(b[1]));
}

// smem: A zh [0,64K) zl [64K,128K); B 3 stages x (eh 16K + el 16K) at OFF_B
#define OFF_B   131072
#define NSTAGE  3
#define DYN_SMEM (1024 + OFF_B + NSTAGE * 32768)   // 230400 <= 227KB cap

__device__ __forceinline__ uint32_t addrA(uint32_t sb, int split, int row, int k) {
    return sb + split * 65536 + row * 512 + ((k * 2) ^ ((row & 7) << 4));
}
__device__ __forceinline__ uint32_t addrB(uint32_t sb, int stage, int half, int row, int k) {
    return sb + OFF_B + stage * 32768 + half * 16384 + row * 128
         + ((k * 2) ^ ((row & 7) << 4));
}

// ---------------------------------------------------------------------------
__global__ void k_prep_A(const float* __restrict__ z) {
    int m = blockIdx.x * 256 + threadIdx.x;
    int b = m >> 11, t = m & 2047;
    const float* p = z + (size_t)b * DD * TT + t;
    double s = 0.0;
#pragma unroll 8
    for (int d = 0; d < DD; d++) { float v = p[(size_t)d * TT]; s += (double)v * v; }
    g_A[m] = (float)s;
}

__global__ void k_prep_z(const float* __restrict__ z) {
    __shared__ float tile[64][65];
    int b = blockIdx.z, d0 = blockIdx.y * 64, t0 = blockIdx.x * 64;
    int tx = threadIdx.x & 63, ty = threadIdx.x >> 6;
    for (int r = ty; r < 64; r += 4)
        tile[r][tx] = z[((size_t)b * DD + d0 + r) * TT + t0 + tx];
    __syncthreads();
    for (int r = ty; r < 64; r += 4) {
        size_t m = (size_t)b * TT + t0 + r;
        float x = tile[tx][r];
        __half h = __float2half(x);
        g_Zh[m * DD + d0 + tx] = h;
        g_Zl[m * DD + d0 + tx] = __float2half((x - __half2float(h)) * LO_SCALE);
    }
}

__global__ void k_prep_emb(const float* __restrict__ emb) {
    int row  = blockIdx.x * 8 + (threadIdx.x >> 5);
    int lane = threadIdx.x & 31;
    const float* p = emb + (size_t)row * DD;
    double s = 0.0;
#pragma unroll
    for (int it = 0; it < 8; it++) {
        int d = it * 32 + lane;
        float x = p[d];
        __half h = __float2half(x);
        g_Eh[(size_t)row * DD + d] = h;
        g_El[(size_t)row * DD + d] = __float2half((x - __half2float(h)) * LO_SCALE);
        s += (double)x * x;
    }
#pragma unroll
    for (int off = 16; off; off >>= 1) s += __shfl_down_sync(0xffffffffu, s, off);
    if (lane == 0) g_Bsq[row] = (float)s;
}

// ---------------------------------------------------------------------------
// Persistent GEMM + fused argmin, 3-stage B pipeline, 1 barrier per chunk.
__global__ void __launch_bounds__(512, 1)
k_mma() {
    extern __shared__ char smem_raw[];
    const uint32_t raw = smem_u32(smem_raw);
    const uint32_t sb  = (raw + 1023) & ~1023u;

    const int tid  = threadIdx.x;
    const int wid  = tid >> 5, lane = tid & 31;
    const int wm   = wid & 3,  wn   = wid >> 2;

    const int u0 = (int)(((long long)blockIdx.x * NUNITS) / NCTA);
    const int u1 = (int)(((long long)(blockIdx.x + 1) * NUNITS) / NCTA);

#define ISSUE_B(J, STAGE, NBASE) do {                                         \
    int _tg = (NBASE) + ((J) >> 2), _c = (J) & 3;                             \
    _Pragma("unroll")                                                         \
    for (int _h = 0; _h < 2; _h++) {                                          \
        const __half* _src = (_h ? g_El : g_Eh)                               \
                           + (size_t)(_tg * NTILE) * DD + _c * KCH;           \
        _Pragma("unroll")                                                     \
        for (int _j = 0; _j < 2; _j++) {                                      \
            int _seg = tid + _j * 512;                                        \
            int _row = _seg >> 3, _sg = _seg & 7;                             \
            cp16(addrB(sb, (STAGE), _h, _row, _sg * 8),                       \
                 _src + (size_t)_row * DD + _sg * 8);                         \
        }                                                                     \
    }                                                                         \
} while (0)

    int prev_tile = -1;
    for (int u = u0; u < u1; u++) {
        const int tile0 = u >> 3;
        const int nbase = (u & 7) * 8;
        const int t0g   = tile0 * MT;

        // prologue: (A if new) + B chunk 0 as group, then B chunk 1 as group
        if (tile0 != prev_tile) {
            prev_tile = tile0;
#pragma unroll
            for (int si = 0; si < 2; si++) {
                const __half* src = (si ? g_Zl : g_Zh) + (size_t)t0g * DD;
#pragma unroll
                for (int j = 0; j < 8; j++) {
                    int seg = tid + j * 512;
                    int row = seg >> 5, sg = seg & 31;
                    cp16(sb + si * 65536 + row * 512 + ((sg * 16) ^ ((row & 7) << 4)),
                         src + (size_t)row * DD + sg * 8);
                }
            }
        }
        ISSUE_B(0, 0, nbase);
        cp_commit();
        ISSUE_B(1, 1, nbase);
        cp_commit();

        float av[4];
        {
            int r0 = wm * 32 + (lane >> 2);
            av[0] = g_A[t0g + r0];      av[1] = g_A[t0g + r0 + 8];
            av[2] = g_A[t0g + r0 + 16]; av[3] = g_A[t0g + r0 + 24];
        }
        float bestd[4]; int besti[4];
#pragma unroll
        for (int k = 0; k < 4; k++) { bestd[k] = CUDART_INF_F; besti[k] = 0; }

        float acc0[2][4][4], acc1[2][4][4];

        for (int j = 0; j < 32; j++) {
            const int stage = j % NSTAGE;
            // chunk j arrived for THIS thread; barrier makes it CTA-visible
            // and releases stage (j-1)%3 for the j+2 issue below.
            if (j < 31) cp_wait<1>(); else cp_wait<0>();
            __syncthreads();
            if (j + 2 < 32) { ISSUE_B(j + 2, (j + 2) % NSTAGE, nbase); cp_commit(); }

            const int tileg = nbase + (j >> 2), c = j & 3;
            if (c == 0) {
#pragma unroll
                for (int mt = 0; mt < 2; mt++)
#pragma unroll
                    for (int nt = 0; nt < 4; nt++)
#pragma unroll
                        for (int q = 0; q < 4; q++) {
                            acc0[mt][nt][q] = 0.0f; acc1[mt][nt][q] = 0.0f;
                        }
            }
#pragma unroll
            for (int k16 = 0; k16 < 4; k16++) {
                const int kloc  = k16 * 16;
                const int kglob = c * KCH + kloc;
                uint32_t ah[2][4], al[2][4];
#pragma unroll
                for (int mt = 0; mt < 2; mt++) {
                    const int row = wm * 32 + mt * 16 + (lane & 15);
                    const int col = kglob + ((lane >> 4) << 3);
                    ldsm4(ah[mt], addrA(sb, 0, row, col));
                    ldsm4(al[mt], addrA(sb, 1, row, col));
                }
                uint32_t beh[4][2], bel[4][2];
#pragma unroll
                for (int ntp = 0; ntp < 2; ntp++) {
                    const int g   = lane >> 3;
                    const int row = wn * 32 + ntp * 16 + ((g >> 1) << 3) + (lane & 7);
                    const int col = kloc + ((g & 1) << 3);
                    uint32_t r4[4];
                    ldsm4(r4, addrB(sb, stage, 0, row, col));
                    beh[ntp * 2][0] = r4[0]; beh[ntp * 2][1] = r4[1];
                    beh[ntp * 2 + 1][0] = r4[2]; beh[ntp * 2 + 1][1] = r4[3];
                    ldsm4(r4, addrB(sb, stage, 1, row, col));
                    bel[ntp * 2][0] = r4[0]; bel[ntp * 2][1] = r4[1];
                    bel[ntp * 2 + 1][0] = r4[2]; bel[ntp * 2 + 1][1] = r4[3];
                }
                // pass-separated: RAW distance on acc1 goes 1 -> 8
#pragma unroll
                for (int mt = 0; mt < 2; mt++)
#pragma unroll
                    for (int nt = 0; nt < 4; nt++)
                        mma16816(acc0[mt][nt], ah[mt], beh[nt]);
#pragma unroll
                for (int mt = 0; mt < 2; mt++)
#pragma unroll
                    for (int nt = 0; nt < 4; nt++)
                        mma16816(acc1[mt][nt], ah[mt], bel[nt]);
#pragma unroll
                for (int mt = 0; mt < 2; mt++)
#pragma unroll
                    for (int nt = 0; nt < 4; nt++)
                        mma16816(acc1[mt][nt], al[mt], beh[nt]);
            }

            if (c == 3) {
                const int nb = tileg * NTILE + wn * 32 + (lane & 3) * 2;
#pragma unroll
                for (int nt = 0; nt < 4; nt++) {
                    const int n0 = nb + nt * 8;
                    const float bq0 = __ldg(&g_Bsq[n0]);
                    const float bq1 = __ldg(&g_Bsq[n0 + 1]);
#pragma unroll
                    for (int mt = 0; mt < 2; mt++) {
                        const float a00 = acc0[mt][nt][0] + acc1[mt][nt][0] * LO_UNSCALE;
                        const float a01 = acc0[mt][nt][1] + acc1[mt][nt][1] * LO_UNSCALE;
                        const float a10 = acc0[mt][nt][2] + acc1[mt][nt][2] * LO_UNSCALE;
                        const float a11 = acc0[mt][nt][3] + acc1[mt][nt][3] * LO_UNSCALE;
                        const int r0 = mt * 2, r1 = mt * 2 + 1;
                        float d;
                        d = fmaf(-2.0f, a00, av[r0] + bq0);
                        if (d < bestd[r0]) { bestd[r0] = d; besti[r0] = n0; }
                        d = fmaf(-2.0f, a01, av[r0] + bq1);
                        if (d < bestd[r0]) { bestd[r0] = d; besti[r0] = n0 + 1; }
                        d = fmaf(-2.0f, a10, av[r1] + bq0);
                        if (d < bestd[r1]) { bestd[r1] = d; besti[r1] = n0; }
                        d = fmaf(-2.0f, a11, av[r1] + bq1);
                        if (d < bestd[r1]) { bestd[r1] = d; besti[r1] = n0 + 1; }
                    }
                }
            }
        }

        // release stages read in the last chunks before next unit's prologue
        __syncthreads();

#pragma unroll
        for (int k = 0; k < 4; k++) {
#pragma unroll
            for (int off = 1; off <= 2; off <<= 1) {
                float od = __shfl_xor_sync(0xffffffffu, bestd[k], off);
                int   oi = __shfl_xor_sync(0xffffffffu, besti[k], off);
                if (od < bestd[k] || (od == bestd[k] && oi < besti[k])) {
                    bestd[k] = od; besti[k] = oi;
                }
            }
        }
        if ((lane & 3) == 0) {
            const int rb = wm * 32 + (lane >> 2);
#pragma unroll
            for (int k = 0; k < 4; k++) {
                const int row = rb + ((k & 1) ? 8 : 0) + ((k >> 1) ? 16 : 0);
                const size_t o = (size_t)(t0g + row) * (NBLK * 4) + (u & 7) * 4 + wn;
                g_pd[o] = bestd[k];
                g_pi[o] = besti[k];
            }
        }
    }
#undef ISSUE_B
}

// ---------------------------------------------------------------------------
__global__ void k_merge(float* __restrict__ out) {
    int m = blockIdx.x * 256 + threadIdx.x;
    const float* pd = g_pd + (size_t)m * 32;
    const int*   pi = g_pi + (size_t)m * 32;
    float bd = pd[0]; int bi = pi[0];
#pragma unroll
    for (int x = 1; x < 32; x++) {
        float d2 = pd[x]; int i2 = pi[x];
        if (d2 < bd || (d2 == bd && i2 < bi)) { bd = d2; bi = i2; }
    }
    g_idx[m] = bi;
    out[BDT + 1 + m] = (float)bi;
}

__global__ void k_gather(const float* __restrict__ z,
                         const float* __restrict__ emb,
                         float* __restrict__ out) {
    __shared__ double red[256];
    const size_t stride = (size_t)GATHER_BLOCKS * 256;
    double ls = 0.0;
    for (size_t i = (size_t)blockIdx.x * 256 + threadIdx.x; i < (size_t)BDT; i += stride) {
        int t = (int)(i & 2047);
        int bd = (int)(i >> 11);
        int d = bd & 255, b = bd >> 8;
        int code = g_idx[(b << 11) + t];
        float zp = z[i];
        float zq = emb[(size_t)code * DD + d];
        float diff = zq - zp;
        out[i] = zp + diff;
        ls += (double)(diff * diff);
    }
    red[threadIdx.x] = ls;
    __syncthreads();
#pragma unroll
    for (int s = 128; s; s >>= 1) {
        if (threadIdx.x < s) red[threadIdx.x] += red[threadIdx.x + s];
        __syncthreads();
    }
    if (threadIdx.x == 0) g_part[blockIdx.x] = red[0];
}

__global__ void k_final(float* __restrict__ out) {
    __shared__ double red[256];
    double s = 0.0;
    for (int j = threadIdx.x; j < GATHER_BLOCKS; j += 256) s += g_part[j];
    red[threadIdx.x] = s;
    __syncthreads();
#pragma unroll
    for (int st = 128; st; st >>= 1) {
        if (threadIdx.x < st) red[threadIdx.x] += red[threadIdx.x + st];
        __syncthreads();
    }
    if (threadIdx.x == 0) out[BDT] = (float)(1.25 * red[0] / (double)BDT);
}

// ---------------------------------------------------------------------------
extern "C" void kernel_launch(void* const* d_in, const int* in_sizes, int n_in,
                              void* d_out, int out_size) {
    const float* z   = (const float*)d_in[0];
    const float* emb = (const float*)d_in[1];
    float* out = (float*)d_out;

    cudaFuncSetAttribute(k_mma, cudaFuncAttributeMaxDynamicSharedMemorySize, DYN_SMEM);

    k_prep_A<<<MTOK / 256, 256>>>(z);
    k_prep_z<<<dim3(TT / 64, DD / 64, BB), 256>>>(z);
    k_prep_emb<<<NE / 8, 256>>>(emb);
    k_mma<<<NCTA, 512, DYN_SMEM>>>();
    k_merge<<<MTOK / 256, 256>>>(out);
    k_gather<<<GATHER_BLOCKS, 256>>>(z, emb, out);
    k_final<<<1, 256>>>(out);
}

// round 7
// speedup vs baseline: 1.0197x; 1.0197x over previous
#include <cuda_runtime.h>
#include <cuda_fp16.h>
#include <cstdint>
#include <math_constants.h>

// ---------------------------------------------------------------------------
#define BB   8
#define DD   256
#define TT   2048
#define NE   8192
#define MTOK (BB * TT)        // 16384
#define BDT  (BB * DD * TT)   // 4194304

#define MT    128             // tokens per tile
#define NTILE 128             // codes per N-tile
#define NBLK  8               // n-blocks per token tile (1024 codes each)
#define NUNITS (MTOK / MT * NBLK)   // 1024 work units
#define NCTA  148
#define KCH   64

#define GATHER_BLOCKS 256     // 64 tokens per block
#define LO_SCALE   4096.0f
#define LO_UNSCALE 2.44140625e-4f    // 2^-12

// ---------------------------------------------------------------------------
__device__ float  g_A[MTOK];
__device__ float  g_Bsq[NE];
__device__ int    g_idx[MTOK];
__device__ double g_part[GATHER_BLOCKS];
__device__ __half g_Zh[(size_t)MTOK * DD];
__device__ __half g_Zl[(size_t)MTOK * DD];
__device__ __half g_Eh[(size_t)NE * DD];
__device__ __half g_El[(size_t)NE * DD];
__device__ float  g_pd[(size_t)MTOK * NBLK * 4];
__device__ int    g_pi[(size_t)MTOK * NBLK * 4];

// ---------------------------------------------------------------------------
__device__ __forceinline__ uint32_t smem_u32(const void* p) {
    uint32_t a;
    asm("{ .reg .u64 t; cvta.to.shared.u64 t, %1; cvt.u32.u64 %0, t; }"
        : "=r"(a) : "l"(p));
    return a;
}
__device__ __forceinline__ void cp16(uint32_t dst, const void* src) {
    asm volatile("cp.async.cg.shared.global [%0], [%1], 16;" :: "r"(dst), "l"(src));
}
__device__ __forceinline__ void cp_commit() {
    asm volatile("cp.async.commit_group;" ::: "memory");
}
template <int N>
__device__ __forceinline__ void cp_wait() {
    asm volatile("cp.async.wait_group %0;" :: "n"(N) : "memory");
}
__device__ __forceinline__ void ldsm4(uint32_t* r, uint32_t a) {
    asm volatile("ldmatrix.sync.aligned.m8n8.x4.shared.b16 {%0,%1,%2,%3}, [%4];"
        : "=r"(r[0]), "=r"(r[1]), "=r"(r[2]), "=r"(r[3]) : "r"(a));
}
__device__ __forceinline__ void mma16816(float* d, const uint32_t* a, const uint32_t* b) {
    asm volatile("mma.sync.aligned.m16n8k16.row.col.f32.f16.f16.f32 "
        "{%0,%1,%2,%3}, {%4,%5,%6,%7}, {%8,%9}, {%0,%1,%2,%3};"
        : "+f"(d[0]), "+f"(d[1]), "+f"(d[2]), "+f"(d[3])
        : "r"(a[0]), "r"(a[1]), "r"(a[2]), "r"(a[3]), "r"(b[0]), "r"(b[1]));
}

// smem: A zh [0,64K) zl [64K,128K); B 3 stages x (eh 16K + el 16K) at OFF_B
#define OFF_B   131072
#define NSTAGE  3
#define DYN_SMEM (1024 + OFF_B + NSTAGE * 32768)

__device__ __forceinline__ uint32_t addrA(uint32_t sb, int split, int row, int k) {
    return sb + split * 65536 + row * 512 + ((k * 2) ^ ((row & 7) << 4));
}
__device__ __forceinline__ uint32_t addrB(uint32_t sb, int stage, int half, int row, int k) {
    return sb + OFF_B + stage * 32768 + half * 16384 + row * 128
         + ((k * 2) ^ ((row & 7) << 4));
}

// ---------------------------------------------------------------------------
__global__ void k_prep_A(const float* __restrict__ z) {
    int m = blockIdx.x * 256 + threadIdx.x;
    int b = m >> 11, t = m & 2047;
    const float* p = z + (size_t)b * DD * TT + t;
    double s = 0.0;
#pragma unroll 8
    for (int d = 0; d < DD; d++) { float v = p[(size_t)d * TT]; s += (double)v * v; }
    g_A[m] = (float)s;
}

__global__ void k_prep_z(const float* __restrict__ z) {
    __shared__ float tile[64][65];
    int b = blockIdx.z, d0 = blockIdx.y * 64, t0 = blockIdx.x * 64;
    int tx = threadIdx.x & 63, ty = threadIdx.x >> 6;
    for (int r = ty; r < 64; r += 4)
        tile[r][tx] = z[((size_t)b * DD + d0 + r) * TT + t0 + tx];
    __syncthreads();
    for (int r = ty; r < 64; r += 4) {
        size_t m = (size_t)b * TT + t0 + r;
        float x = tile[tx][r];
        __half h = __float2half(x);
        g_Zh[m * DD + d0 + tx] = h;
        g_Zl[m * DD + d0 + tx] = __float2half((x - __half2float(h)) * LO_SCALE);
    }
}

__global__ void k_prep_emb(const float* __restrict__ emb) {
    int row  = blockIdx.x * 8 + (threadIdx.x >> 5);
    int lane = threadIdx.x & 31;
    const float* p = emb + (size_t)row * DD;
    double s = 0.0;
#pragma unroll
    for (int it = 0; it < 8; it++) {
        int d = it * 32 + lane;
        float x = p[d];
        __half h = __float2half(x);
        g_Eh[(size_t)row * DD + d] = h;
        g_El[(size_t)row * DD + d] = __float2half((x - __half2float(h)) * LO_SCALE);
        s += (double)x * x;
    }
#pragma unroll
    for (int off = 16; off; off >>= 1) s += __shfl_down_sync(0xffffffffu, s, off);
    if (lane == 0) g_Bsq[row] = (float)s;
}

// ---------------------------------------------------------------------------
// Persistent GEMM + fused argmin.
// 256 threads = 8 warps (2 wm x 4 wn); warp tile 64(M) x 32(N) = 4 mt x 4 nt.
__global__ void __launch_bounds__(256, 1)
k_mma() {
    extern __shared__ char smem_raw[];
    const uint32_t raw = smem_u32(smem_raw);
    const uint32_t sb  = (raw + 1023) & ~1023u;

    const int tid  = threadIdx.x;
    const int wid  = tid >> 5, lane = tid & 31;
    const int wm   = wid >> 2, wn   = wid & 3;

    const int u0 = (int)(((long long)blockIdx.x * NUNITS) / NCTA);
    const int u1 = (int)(((long long)(blockIdx.x + 1) * NUNITS) / NCTA);

#define ISSUE_B(J, STAGE, NBASE) do {                                         \
    int _tg = (NBASE) + ((J) >> 2), _c = (J) & 3;                             \
    _Pragma("unroll")                                                         \
    for (int _h = 0; _h < 2; _h++) {                                          \
        const __half* _src = (_h ? g_El : g_Eh)                               \
                           + (size_t)(_tg * NTILE) * DD + _c * KCH;           \
        _Pragma("unroll")                                                     \
        for (int _j = 0; _j < 4; _j++) {                                      \
            int _seg = tid + _j * 256;                                        \
            int _row = _seg >> 3, _sg = _seg & 7;                             \
            cp16(addrB(sb, (STAGE), _h, _row, _sg * 8),                       \
                 _src + (size_t)_row * DD + _sg * 8);                         \
        }                                                                     \
    }                                                                         \
} while (0)

    int prev_tile = -1;
    for (int u = u0; u < u1; u++) {
        const int tile0 = u >> 3;
        const int nbase = (u & 7) * 8;
        const int t0g   = tile0 * MT;

        if (tile0 != prev_tile) {
            prev_tile = tile0;
#pragma unroll
            for (int si = 0; si < 2; si++) {
                const __half* src = (si ? g_Zl : g_Zh) + (size_t)t0g * DD;
#pragma unroll
                for (int j = 0; j < 16; j++) {
                    int seg = tid + j * 256;
                    int row = seg >> 5, sg = seg & 31;
                    cp16(sb + si * 65536 + row * 512 + ((sg * 16) ^ ((row & 7) << 4)),
                         src + (size_t)row * DD + sg * 8);
                }
            }
        }
        ISSUE_B(0, 0, nbase);
        cp_commit();
        ISSUE_B(1, 1, nbase);
        cp_commit();

        float av[8];
        {
#pragma unroll
            for (int mt = 0; mt < 4; mt++) {
                int r0 = wm * 64 + mt * 16 + (lane >> 2);
                av[mt * 2]     = g_A[t0g + r0];
                av[mt * 2 + 1] = g_A[t0g + r0 + 8];
            }
        }
        float bestd[8]; int besti[8];
#pragma unroll
        for (int k = 0; k < 8; k++) { bestd[k] = CUDART_INF_F; besti[k] = 0; }

        float acc0[4][4][4], acc1[4][4][4];

        for (int j = 0; j < 32; j++) {
            const int stage = j % NSTAGE;
            if (j < 31) cp_wait<1>(); else cp_wait<0>();
            __syncthreads();
            if (j + 2 < 32) { ISSUE_B(j + 2, (j + 2) % NSTAGE, nbase); cp_commit(); }

            const int tileg = nbase + (j >> 2), c = j & 3;
            if (c == 0) {
#pragma unroll
                for (int mt = 0; mt < 4; mt++)
#pragma unroll
                    for (int nt = 0; nt < 4; nt++)
#pragma unroll
                        for (int q = 0; q < 4; q++) {
                            acc0[mt][nt][q] = 0.0f; acc1[mt][nt][q] = 0.0f;
                        }
            }
#pragma unroll
            for (int k16 = 0; k16 < 4; k16++) {
                const int kloc  = k16 * 16;
                const int kglob = c * KCH + kloc;
                uint32_t ah[4][4], al[4][4];
#pragma unroll
                for (int mt = 0; mt < 4; mt++) {
                    const int row = wm * 64 + mt * 16 + (lane & 15);
                    const int col = kglob + ((lane >> 4) << 3);
                    ldsm4(ah[mt], addrA(sb, 0, row, col));
                    ldsm4(al[mt], addrA(sb, 1, row, col));
                }
                uint32_t beh[4][2], bel[4][2];
#pragma unroll
                for (int ntp = 0; ntp < 2; ntp++) {
                    const int g   = lane >> 3;
                    const int row = wn * 32 + ntp * 16 + ((g >> 1) << 3) + (lane & 7);
                    const int col = kloc + ((g & 1) << 3);
                    uint32_t r4[4];
                    ldsm4(r4, addrB(sb, stage, 0, row, col));
                    beh[ntp * 2][0] = r4[0]; beh[ntp * 2][1] = r4[1];
                    beh[ntp * 2 + 1][0] = r4[2]; beh[ntp * 2 + 1][1] = r4[3];
                    ldsm4(r4, addrB(sb, stage, 1, row, col));
                    bel[ntp * 2][0] = r4[0]; bel[ntp * 2][1] = r4[1];
                    bel[ntp * 2 + 1][0] = r4[2]; bel[ntp * 2 + 1][1] = r4[3];
                }
#pragma unroll
                for (int mt = 0; mt < 4; mt++)
#pragma unroll
                    for (int nt = 0; nt < 4; nt++)
                        mma16816(acc0[mt][nt], ah[mt], beh[nt]);
#pragma unroll
                for (int mt = 0; mt < 4; mt++)
#pragma unroll
                    for (int nt = 0; nt < 4; nt++)
                        mma16816(acc1[mt][nt], ah[mt], bel[nt]);
#pragma unroll
                for (int mt = 0; mt < 4; mt++)
#pragma unroll
                    for (int nt = 0; nt < 4; nt++)
                        mma16816(acc1[mt][nt], al[mt], beh[nt]);
            }

            if (c == 3) {
                const int nb = tileg * NTILE + wn * 32 + (lane & 3) * 2;
#pragma unroll
                for (int nt = 0; nt < 4; nt++) {
                    const int n0 = nb + nt * 8;
                    const float bq0 = __ldg(&g_Bsq[n0]);
                    const float bq1 = __ldg(&g_Bsq[n0 + 1]);
#pragma unroll
                    for (int mt = 0; mt < 4; mt++) {
                        const float a00 = acc0[mt][nt][0] + acc1[mt][nt][0] * LO_UNSCALE;
                        const float a01 = acc0[mt][nt][1] + acc1[mt][nt][1] * LO_UNSCALE;
                        const float a10 = acc0[mt][nt][2] + acc1[mt][nt][2] * LO_UNSCALE;
                        const float a11 = acc0[mt][nt][3] + acc1[mt][nt][3] * LO_UNSCALE;
                        const int r0 = mt * 2, r1 = mt * 2 + 1;
                        float d;
                        d = fmaf(-2.0f, a00, av[r0] + bq0);
                        if (d < bestd[r0]) { bestd[r0] = d; besti[r0] = n0; }
                        d = fmaf(-2.0f, a01, av[r0] + bq1);
                        if (d < bestd[r0]) { bestd[r0] = d; besti[r0] = n0 + 1; }
                        d = fmaf(-2.0f, a10, av[r1] + bq0);
                        if (d < bestd[r1]) { bestd[r1] = d; besti[r1] = n0; }
                        d = fmaf(-2.0f, a11, av[r1] + bq1);
                        if (d < bestd[r1]) { bestd[r1] = d; besti[r1] = n0 + 1; }
                    }
                }
            }
        }

        __syncthreads();

#pragma unroll
        for (int k = 0; k < 8; k++) {
#pragma unroll
            for (int off = 1; off <= 2; off <<= 1) {
                float od = __shfl_xor_sync(0xffffffffu, bestd[k], off);
                int   oi = __shfl_xor_sync(0xffffffffu, besti[k], off);
                if (od < bestd[k] || (od == bestd[k] && oi < besti[k])) {
                    bestd[k] = od; besti[k] = oi;
                }
            }
        }
        if ((lane & 3) == 0) {
#pragma unroll
            for (int k = 0; k < 8; k++) {
                const int mt = k >> 1, h = k & 1;
                const int row = wm * 64 + mt * 16 + (lane >> 2) + h * 8;
                const size_t o = (size_t)(t0g + row) * (NBLK * 4) + (u & 7) * 4 + wn;
                g_pd[o] = bestd[k];
                g_pi[o] = besti[k];
            }
        }
    }
#undef ISSUE_B
}

// ---------------------------------------------------------------------------
__global__ void k_merge(float* __restrict__ out) {
    int m = blockIdx.x * 256 + threadIdx.x;
    const float* pd = g_pd + (size_t)m * 32;
    const int*   pi = g_pi + (size_t)m * 32;
    float bd = pd[0]; int bi = pi[0];
#pragma unroll
    for (int x = 1; x < 32; x++) {
        float d2 = pd[x]; int i2 = pi[x];
        if (d2 < bd || (d2 == bd && i2 < bi)) { bd = d2; bi = i2; }
    }
    g_idx[m] = bi;
    out[BDT + 1 + m] = (float)bi;
}

// ---------------------------------------------------------------------------
// Gather: CTA = 64 tokens; stage their emb rows in smem (conflict-free pad),
// then stream z/out coalesced. 256 blocks x 256 threads.
__global__ void __launch_bounds__(256)
k_gather(const float* __restrict__ z,
         const float* __restrict__ emb,
         float* __restrict__ out) {
    __shared__ float erow[64 * 257];
    __shared__ int   codes[64];
    __shared__ double red[256];

    const int tid = threadIdx.x;
    const int m0  = blockIdx.x * 64;          // first token; b constant in block
    const int b   = m0 >> 11;
    const int t0  = m0 & 2047;

    if (tid < 64) codes[tid] = g_idx[m0 + tid];
    __syncthreads();
    // stage 64 emb rows (coalesced 1KB rows)
#pragma unroll
    for (int it = 0; it < 64; it++) {
        int idx = it * 256 + tid;
        int row = idx >> 8, col = idx & 255;
        erow[row * 257 + col] = emb[(size_t)codes[row] * DD + col];
    }
    __syncthreads();

    const float* zb = z   + ((size_t)b * DD) * TT + t0;
    float*       ob = out + ((size_t)b * DD) * TT + t0;
    double ls = 0.0;
#pragma unroll 4
    for (int it = 0; it < 64; it++) {
        int idx = it * 256 + tid;
        int d = idx >> 6, tt = idx & 63;
        float zp = zb[(size_t)d * TT + tt];
        float zq = erow[tt * 257 + d];
        float diff = zq - zp;                 // fl(zq - zp), reference shape
        ob[(size_t)d * TT + tt] = zp + diff;  // STE
        ls += (double)(diff * diff);
    }
    red[tid] = ls;
    __syncthreads();
#pragma unroll
    for (int s = 128; s; s >>= 1) {
        if (tid < s) red[tid] += red[tid + s];
        __syncthreads();
    }
    if (tid == 0) g_part[blockIdx.x] = red[0];
}

__global__ void k_final(float* __restrict__ out) {
    __shared__ double red[256];
    double s = (threadIdx.x < GATHER_BLOCKS) ? g_part[threadIdx.x] : 0.0;
    red[threadIdx.x] = s;
    __syncthreads();
#pragma unroll
    for (int st = 128; st; st >>= 1) {
        if (threadIdx.x < st) red[threadIdx.x] += red[threadIdx.x + st];
        __syncthreads();
    }
    if (threadIdx.x == 0) out[BDT] = (float)(1.25 * red[0] / (double)BDT);
}

// ---------------------------------------------------------------------------
extern "C" void kernel_launch(void* const* d_in, const int* in_sizes, int n_in,
                              void* d_out, int out_size) {
    const float* z   = (const float*)d_in[0];
    const float* emb = (const float*)d_in[1];
    float* out = (float*)d_out;

    cudaFuncSetAttribute(k_mma, cudaFuncAttributeMaxDynamicSharedMemorySize, DYN_SMEM);

    k_prep_A<<<MTOK / 256, 256>>>(z);
    k_prep_z<<<dim3(TT / 64, DD / 64, BB), 256>>>(z);
    k_prep_emb<<<NE / 8, 256>>>(emb);
    k_mma<<<NCTA, 256, DYN_SMEM>>>();
    k_merge<<<MTOK / 256, 256>>>(out);
    k_gather<<<GATHER_BLOCKS, 256>>>(z, emb, out);
    k_final<<<1, 256>>>(out);
}

// round 8
// speedup vs baseline: 1.0388x; 1.0187x over previous
#include <cuda_runtime.h>
#include <cuda_fp16.h>
#include <cstdint>
#include <math_constants.h>

// ---------------------------------------------------------------------------
#define BB   8
#define DD   256
#define TT   2048
#define NE   8192
#define MTOK (BB * TT)        // 16384
#define BDT  (BB * DD * TT)   // 4194304

#define MT    128             // tokens per tile
#define NTILE 128             // codes per N-tile
#define NBLK  8               // n-blocks per token tile (1024 codes each)
#define NUNITS (MTOK / MT * NBLK)   // 1024 work units
#define NCTA  148
#define KCH   64

#define GATHER_BLOCKS 256     // 64 tokens per block
#define LO_SCALE   4096.0f
#define LO_UNSCALE 2.44140625e-4f    // 2^-12

// ---------------------------------------------------------------------------
__device__ float  g_A[MTOK];
__device__ float  g_Bsq[NE];
__device__ double g_part[GATHER_BLOCKS];
__device__ __half g_Zh[(size_t)MTOK * DD];
__device__ __half g_Zl[(size_t)MTOK * DD];
__device__ __half g_Eh[(size_t)NE * DD];
__device__ __half g_El[(size_t)NE * DD];
// partials transposed: [x][m], x = nblk*4 + wn  (coalesced write AND read)
__device__ float  g_pd[32 * (size_t)MTOK];
__device__ int    g_pi[32 * (size_t)MTOK];

// ---------------------------------------------------------------------------
__device__ __forceinline__ uint32_t smem_u32(const void* p) {
    uint32_t a;
    asm("{ .reg .u64 t; cvta.to.shared.u64 t, %1; cvt.u32.u64 %0, t; }"
        : "=r"(a) : "l"(p));
    return a;
}
__device__ __forceinline__ void cp16(uint32_t dst, const void* src) {
    asm volatile("cp.async.cg.shared.global [%0], [%1], 16;" :: "r"(dst), "l"(src));
}
__device__ __forceinline__ void cp_commit() {
    asm volatile("cp.async.commit_group;" ::: "memory");
}
template <int N>
__device__ __forceinline__ void cp_wait() {
    asm volatile("cp.async.wait_group %0;" :: "n"(N) : "memory");
}
__device__ __forceinline__ void ldsm4(uint32_t* r, uint32_t a) {
    asm volatile("ldmatrix.sync.aligned.m8n8.x4.shared.b16 {%0,%1,%2,%3}, [%4];"
        : "=r"(r[0]), "=r"(r[1]), "=r"(r[2]), "=r"(r[3]) : "r"(a));
}
__device__ __forceinline__ void mma16816(float* d, const uint32_t* a, const uint32_t* b) {
    asm volatile("mma.sync.aligned.m16n8k16.row.col.f32.f16.f16.f32 "
        "{%0,%1,%2,%3}, {%4,%5,%6,%7}, {%8,%9}, {%0,%1,%2,%3};"
        : "+f"(d[0]), "+f"(d[1]), "+f"(d[2]), "+f"(d[3])
        : "r"(a[0]), "r"(a[1]), "r"(a[2]), "r"(a[3]), "r"(b[0]), "r"(b[1]));
}

// smem: A zh [0,64K) zl [64K,128K); B 3 stages x (eh 16K + el 16K) at OFF_B
#define OFF_B   131072
#define NSTAGE  3
#define DYN_SMEM (1024 + OFF_B + NSTAGE * 32768)

__device__ __forceinline__ uint32_t addrA(uint32_t sb, int split, int row, int k) {
    return sb + split * 65536 + row * 512 + ((k * 2) ^ ((row & 7) << 4));
}
__device__ __forceinline__ uint32_t addrB(uint32_t sb, int stage, int half, int row, int k) {
    return sb + OFF_B + stage * 32768 + half * 16384 + row * 128
         + ((k * 2) ^ ((row & 7) << 4));
}

// ---------------------------------------------------------------------------
__global__ void k_prep_A(const float* __restrict__ z) {
    int m = blockIdx.x * 256 + threadIdx.x;
    int b = m >> 11, t = m & 2047;
    const float* p = z + (size_t)b * DD * TT + t;
    double s = 0.0;
#pragma unroll 8
    for (int d = 0; d < DD; d++) { float v = p[(size_t)d * TT]; s += (double)v * v; }
    g_A[m] = (float)s;
}

__global__ void k_prep_z(const float* __restrict__ z) {
    __shared__ float tile[64][65];
    int b = blockIdx.z, d0 = blockIdx.y * 64, t0 = blockIdx.x * 64;
    int tx = threadIdx.x & 63, ty = threadIdx.x >> 6;
    for (int r = ty; r < 64; r += 4)
        tile[r][tx] = z[((size_t)b * DD + d0 + r) * TT + t0 + tx];
    __syncthreads();
    for (int r = ty; r < 64; r += 4) {
        size_t m = (size_t)b * TT + t0 + r;
        float x = tile[tx][r];
        __half h = __float2half(x);
        g_Zh[m * DD + d0 + tx] = h;
        g_Zl[m * DD + d0 + tx] = __float2half((x - __half2float(h)) * LO_SCALE);
    }
}

__global__ void k_prep_emb(const float* __restrict__ emb) {
    int row  = blockIdx.x * 8 + (threadIdx.x >> 5);
    int lane = threadIdx.x & 31;
    const float* p = emb + (size_t)row * DD;
    double s = 0.0;
#pragma unroll
    for (int it = 0; it < 8; it++) {
        int d = it * 32 + lane;
        float x = p[d];
        __half h = __float2half(x);
        g_Eh[(size_t)row * DD + d] = h;
        g_El[(size_t)row * DD + d] = __float2half((x - __half2float(h)) * LO_SCALE);
        s += (double)x * x;
    }
#pragma unroll
    for (int off = 16; off; off >>= 1) s += __shfl_down_sync(0xffffffffu, s, off);
    if (lane == 0) g_Bsq[row] = (float)s;
}

// ---------------------------------------------------------------------------
// Persistent GEMM + fused argmin.
// 256 threads = 8 warps (2 wm x 4 wn); warp tile 64(M) x 32(N).
__global__ void __launch_bounds__(256, 1)
k_mma() {
    extern __shared__ char smem_raw[];
    const uint32_t raw = smem_u32(smem_raw);
    const uint32_t sb  = (raw + 1023) & ~1023u;

    const int tid  = threadIdx.x;
    const int wid  = tid >> 5, lane = tid & 31;
    const int wm   = wid >> 2, wn   = wid & 3;

    const int u0 = (int)(((long long)blockIdx.x * NUNITS) / NCTA);
    const int u1 = (int)(((long long)(blockIdx.x + 1) * NUNITS) / NCTA);

#define ISSUE_B(J, STAGE, NBASE) do {                                         \
    int _tg = (NBASE) + ((J) >> 2), _c = (J) & 3;                             \
    _Pragma("unroll")                                                         \
    for (int _h = 0; _h < 2; _h++) {                                          \
        const __half* _src = (_h ? g_El : g_Eh)                               \
                           + (size_t)(_tg * NTILE) * DD + _c * KCH;           \
        _Pragma("unroll")                                                     \
        for (int _j = 0; _j < 4; _j++) {                                      \
            int _seg = tid + _j * 256;                                        \
            int _row = _seg >> 3, _sg = _seg & 7;                             \
            cp16(addrB(sb, (STAGE), _h, _row, _sg * 8),                       \
                 _src + (size_t)_row * DD + _sg * 8);                         \
        }                                                                     \
    }                                                                         \
} while (0)

    int prev_tile = -1;
    for (int u = u0; u < u1; u++) {
        const int tile0 = u >> 3;
        const int nbase = (u & 7) * 8;
        const int t0g   = tile0 * MT;

        if (tile0 != prev_tile) {
            prev_tile = tile0;
#pragma unroll
            for (int si = 0; si < 2; si++) {
                const __half* src = (si ? g_Zl : g_Zh) + (size_t)t0g * DD;
#pragma unroll
                for (int j = 0; j < 16; j++) {
                    int seg = tid + j * 256;
                    int row = seg >> 5, sg = seg & 31;
                    cp16(sb + si * 65536 + row * 512 + ((sg * 16) ^ ((row & 7) << 4)),
                         src + (size_t)row * DD + sg * 8);
                }
            }
        }
        ISSUE_B(0, 0, nbase);
        cp_commit();
        ISSUE_B(1, 1, nbase);
        cp_commit();

        float av[8];
#pragma unroll
        for (int mt = 0; mt < 4; mt++) {
            int r0 = wm * 64 + mt * 16 + (lane >> 2);
            av[mt * 2]     = g_A[t0g + r0];
            av[mt * 2 + 1] = g_A[t0g + r0 + 8];
        }
        float bestd[8]; int besti[8];
#pragma unroll
        for (int k = 0; k < 8; k++) { bestd[k] = CUDART_INF_F; besti[k] = 0; }

        float acc0[4][4][4], acc1[4][4][4];

        for (int j = 0; j < 32; j++) {
            const int stage = j % NSTAGE;
            if (j < 31) cp_wait<1>(); else cp_wait<0>();
            __syncthreads();
            if (j + 2 < 32) { ISSUE_B(j + 2, (j + 2) % NSTAGE, nbase); cp_commit(); }

            const int tileg = nbase + (j >> 2), c = j & 3;
            if (c == 0) {
#pragma unroll
                for (int mt = 0; mt < 4; mt++)
#pragma unroll
                    for (int nt = 0; nt < 4; nt++)
#pragma unroll
                        for (int q = 0; q < 4; q++) {
                            acc0[mt][nt][q] = 0.0f; acc1[mt][nt][q] = 0.0f;
                        }
            }
#pragma unroll
            for (int k16 = 0; k16 < 4; k16++) {
                const int kloc  = k16 * 16;
                const int kglob = c * KCH + kloc;
                uint32_t ah[4][4], al[4][4], beh[4][2], bel[4][2];

                // phase 1: operands for pass0 only (beh, ah)
#pragma unroll
                for (int ntp = 0; ntp < 2; ntp++) {
                    const int g   = lane >> 3;
                    const int row = wn * 32 + ntp * 16 + ((g >> 1) << 3) + (lane & 7);
                    const int col = kloc + ((g & 1) << 3);
                    uint32_t r4[4];
                    ldsm4(r4, addrB(sb, stage, 0, row, col));
                    beh[ntp * 2][0] = r4[0]; beh[ntp * 2][1] = r4[1];
                    beh[ntp * 2 + 1][0] = r4[2]; beh[ntp * 2 + 1][1] = r4[3];
                }
#pragma unroll
                for (int mt = 0; mt < 4; mt++) {
                    const int row = wm * 64 + mt * 16 + (lane & 15);
                    const int col = kglob + ((lane >> 4) << 3);
                    ldsm4(ah[mt], addrA(sb, 0, row, col));
                }
                // pass0: acc0 += ah*beh (LDSMs for pass1/2 fly underneath)
#pragma unroll
                for (int mt = 0; mt < 4; mt++)
#pragma unroll
                    for (int nt = 0; nt < 4; nt++)
                        mma16816(acc0[mt][nt], ah[mt], beh[nt]);

                // phase 2: operands for pass1/2 (bel, al), hidden under pass0
#pragma unroll
                for (int ntp = 0; ntp < 2; ntp++) {
                    const int g   = lane >> 3;
                    const int row = wn * 32 + ntp * 16 + ((g >> 1) << 3) + (lane & 7);
                    const int col = kloc + ((g & 1) << 3);
                    uint32_t r4[4];
                    ldsm4(r4, addrB(sb, stage, 1, row, col));
                    bel[ntp * 2][0] = r4[0]; bel[ntp * 2][1] = r4[1];
                    bel[ntp * 2 + 1][0] = r4[2]; bel[ntp * 2 + 1][1] = r4[3];
                }
#pragma unroll
                for (int mt = 0; mt < 4; mt++) {
                    const int row = wm * 64 + mt * 16 + (lane & 15);
                    const int col = kglob + ((lane >> 4) << 3);
                    ldsm4(al[mt], addrA(sb, 1, row, col));
                }
#pragma unroll
                for (int mt = 0; mt < 4; mt++)
#pragma unroll
                    for (int nt = 0; nt < 4; nt++)
                        mma16816(acc1[mt][nt], ah[mt], bel[nt]);
#pragma unroll
                for (int mt = 0; mt < 4; mt++)
#pragma unroll
                    for (int nt = 0; nt < 4; nt++)
                        mma16816(acc1[mt][nt], al[mt], beh[nt]);
            }

            if (c == 3) {
                const int nb = tileg * NTILE + wn * 32 + (lane & 3) * 2;
#pragma unroll
                for (int nt = 0; nt < 4; nt++) {
                    const int n0 = nb + nt * 8;
                    const float bq0 = __ldg(&g_Bsq[n0]);
                    const float bq1 = __ldg(&g_Bsq[n0 + 1]);
#pragma unroll
                    for (int mt = 0; mt < 4; mt++) {
                        const float a00 = acc0[mt][nt][0] + acc1[mt][nt][0] * LO_UNSCALE;
                        const float a01 = acc0[mt][nt][1] + acc1[mt][nt][1] * LO_UNSCALE;
                        const float a10 = acc0[mt][nt][2] + acc1[mt][nt][2] * LO_UNSCALE;
                        const float a11 = acc0[mt][nt][3] + acc1[mt][nt][3] * LO_UNSCALE;
                        const int r0 = mt * 2, r1 = mt * 2 + 1;
                        float d;
                        d = fmaf(-2.0f, a00, av[r0] + bq0);
                        if (d < bestd[r0]) { bestd[r0] = d; besti[r0] = n0; }
                        d = fmaf(-2.0f, a01, av[r0] + bq1);
                        if (d < bestd[r0]) { bestd[r0] = d; besti[r0] = n0 + 1; }
                        d = fmaf(-2.0f, a10, av[r1] + bq0);
                        if (d < bestd[r1]) { bestd[r1] = d; besti[r1] = n0; }
                        d = fmaf(-2.0f, a11, av[r1] + bq1);
                        if (d < bestd[r1]) { bestd[r1] = d; besti[r1] = n0 + 1; }
                    }
                }
            }
        }

        __syncthreads();

#pragma unroll
        for (int k = 0; k < 8; k++) {
#pragma unroll
            for (int off = 1; off <= 2; off <<= 1) {
                float od = __shfl_xor_sync(0xffffffffu, bestd[k], off);
                int   oi = __shfl_xor_sync(0xffffffffu, besti[k], off);
                if (od < bestd[k] || (od == bestd[k] && oi < besti[k])) {
                    bestd[k] = od; besti[k] = oi;
                }
            }
        }
        if ((lane & 3) == 0) {
            const size_t xo = (size_t)((u & 7) * 4 + wn) * MTOK + t0g;
#pragma unroll
            for (int k = 0; k < 8; k++) {
                const int mt = k >> 1, h = k & 1;
                const int row = wm * 64 + mt * 16 + (lane >> 2) + h * 8;
                g_pd[xo + row] = bestd[k];
                g_pi[xo + row] = besti[k];
            }
        }
    }
#undef ISSUE_B
}

// ---------------------------------------------------------------------------
// Fused merge + gather + STE + loss. Block = 64 tokens.
__global__ void __launch_bounds__(256)
k_gather(const float* __restrict__ z,
         const float* __restrict__ emb,
         float* __restrict__ out) {
    __shared__ float erow[64 * 257];
    __shared__ int   codes[64];
    __shared__ double red[256];

    const int tid = threadIdx.x;
    const int m0  = blockIdx.x * 64;
    const int b   = m0 >> 11;
    const int t0  = m0 & 2047;

    // merge 32 partials per token (coalesced: consecutive tid -> consecutive m)
    if (tid < 64) {
        const int m = m0 + tid;
        float bd = g_pd[m]; int bi = g_pi[m];
#pragma unroll
        for (int x = 1; x < 32; x++) {
            float d2 = g_pd[(size_t)x * MTOK + m];
            int   i2 = g_pi[(size_t)x * MTOK + m];
            if (d2 < bd || (d2 == bd && i2 < bi)) { bd = d2; bi = i2; }
        }
        codes[tid] = bi;
        out[BDT + 1 + m] = (float)bi;
    }
    __syncthreads();

    // stage 64 emb rows (coalesced 1KB rows, padded for conflict-free reads)
#pragma unroll
    for (int it = 0; it < 64; it++) {
        int idx = it * 256 + tid;
        int row = idx >> 8, col = idx & 255;
        erow[row * 257 + col] = emb[(size_t)codes[row] * DD + col];
    }
    __syncthreads();

    const float* zb = z   + ((size_t)b * DD) * TT + t0;
    float*       ob = out + ((size_t)b * DD) * TT + t0;
    double ls = 0.0;
#pragma unroll 4
    for (int it = 0; it < 64; it++) {
        int idx = it * 256 + tid;
        int d = idx >> 6, tt = idx & 63;
        float zp = zb[(size_t)d * TT + tt];
        float zq = erow[tt * 257 + d];
        float diff = zq - zp;                 // fl(zq - zp), reference shape
        ob[(size_t)d * TT + tt] = zp + diff;  // STE
        ls += (double)(diff * diff);
    }
    red[tid] = ls;
    __syncthreads();
#pragma unroll
    for (int s = 128; s; s >>= 1) {
        if (tid < s) red[tid] += red[tid + s];
        __syncthreads();
    }
    if (tid == 0) g_part[blockIdx.x] = red[0];
}

__global__ void k_final(float* __restrict__ out) {
    __shared__ double red[256];
    double s = (threadIdx.x < GATHER_BLOCKS) ? g_part[threadIdx.x] : 0.0;
    red[threadIdx.x] = s;
    __syncthreads();
#pragma unroll
    for (int st = 128; st; st >>= 1) {
        if (threadIdx.x < st) red[threadIdx.x] += red[threadIdx.x + st];
        __syncthreads();
    }
    if (threadIdx.x == 0) out[BDT] = (float)(1.25 * red[0] / (double)BDT);
}

// ---------------------------------------------------------------------------
extern "C" void kernel_launch(void* const* d_in, const int* in_sizes, int n_in,
                              void* d_out, int out_size) {
    const float* z   = (const float*)d_in[0];
    const float* emb = (const float*)d_in[1];
    float* out = (float*)d_out;

    cudaFuncSetAttribute(k_mma, cudaFuncAttributeMaxDynamicSharedMemorySize, DYN_SMEM);

    k_prep_A<<<MTOK / 256, 256>>>(z);
    k_prep_z<<<dim3(TT / 64, DD / 64, BB), 256>>>(z);
    k_prep_emb<<<NE / 8, 256>>>(emb);
    k_mma<<<NCTA, 256, DYN_SMEM>>>();
    k_gather<<<GATHER_BLOCKS, 256>>>(z, emb, out);
    k_final<<<1, 256>>>(out);
}

// round 9
// speedup vs baseline: 1.0688x; 1.0289x over previous
#include <cuda_runtime.h>
#include <cuda_fp16.h>
#include <cstdint>
#include <math_constants.h>

// ---------------------------------------------------------------------------
#define BB   8
#define DD   256
#define TT   2048
#define NE   8192
#define MTOK (BB * TT)        // 16384
#define BDT  (BB * DD * TT)   // 4194304

#define MT    128             // tokens per tile
#define NTILE 128             // codes per N-tile
#define NBLK  8               // n-blocks per token tile (1024 codes each)
#define NUNITS (MTOK / MT * NBLK)   // 1024 work units
#define NCTA  148
#define KCH   64

#define GATHER_BLOCKS 256     // 64 tokens per block
#define LO_SCALE   4096.0f
#define LO_UNSCALE 2.44140625e-4f    // 2^-12

// ---------------------------------------------------------------------------
__device__ double g_Ap[4][MTOK];      // ||z||^2 quad partials (fp64, fixed order)
__device__ float  g_Bsq[NE];
__device__ double g_part[GATHER_BLOCKS];
__device__ __half g_Zh[(size_t)MTOK * DD];
__device__ __half g_Zl[(size_t)MTOK * DD];
__device__ __half g_Eh[(size_t)NE * DD];
__device__ __half g_El[(size_t)NE * DD];
// partials transposed: [x][m], x = nblk*4 + wn  (coalesced write AND read)
__device__ float  g_pd[32 * (size_t)MTOK];
__device__ int    g_pi[32 * (size_t)MTOK];

// ---------------------------------------------------------------------------
__device__ __forceinline__ uint32_t smem_u32(const void* p) {
    uint32_t a;
    asm("{ .reg .u64 t; cvta.to.shared.u64 t, %1; cvt.u32.u64 %0, t; }"
        : "=r"(a) : "l"(p));
    return a;
}
__device__ __forceinline__ void cp16(uint32_t dst, const void* src) {
    asm volatile("cp.async.cg.shared.global [%0], [%1], 16;" :: "r"(dst), "l"(src));
}
__device__ __forceinline__ void cp_commit() {
    asm volatile("cp.async.commit_group;" ::: "memory");
}
template <int N>
__device__ __forceinline__ void cp_wait() {
    asm volatile("cp.async.wait_group %0;" :: "n"(N) : "memory");
}
__device__ __forceinline__ void ldsm4(uint32_t* r, uint32_t a) {
    asm volatile("ldmatrix.sync.aligned.m8n8.x4.shared.b16 {%0,%1,%2,%3}, [%4];"
        : "=r"(r[0]), "=r"(r[1]), "=r"(r[2]), "=r"(r[3]) : "r"(a));
}
__device__ __forceinline__ void mma16816(float* d, const uint32_t* a, const uint32_t* b) {
    asm volatile("mma.sync.aligned.m16n8k16.row.col.f32.f16.f16.f32 "
        "{%0,%1,%2,%3}, {%4,%5,%6,%7}, {%8,%9}, {%0,%1,%2,%3};"
        : "+f"(d[0]), "+f"(d[1]), "+f"(d[2]), "+f"(d[3])
        : "r"(a[0]), "r"(a[1]), "r"(a[2]), "r"(a[3]), "r"(b[0]), "r"(b[1]));
}

// smem: A zh [0,64K) zl [64K,128K); B 3 stages x (eh 16K + el 16K) at OFF_B
#define OFF_B   131072
#define NSTAGE  3
#define DYN_SMEM (1024 + OFF_B + NSTAGE * 32768)

__device__ __forceinline__ uint32_t addrA(uint32_t sb, int split, int row, int k) {
    return sb + split * 65536 + row * 512 + ((k * 2) ^ ((row & 7) << 4));
}
__device__ __forceinline__ uint32_t addrB(uint32_t sb, int stage, int half, int row, int k) {
    return sb + OFF_B + stage * 32768 + half * 16384 + row * 128
         + ((k * 2) ^ ((row & 7) << 4));
}

// ---------------------------------------------------------------------------
// Fused prep: blocks [0,1024) transpose+split z AND compute ||z||^2 partials;
// blocks [1024,2048) split emb + compute ||e||^2. One launch fills the chip.
__global__ void __launch_bounds__(256)
k_prep(const float* __restrict__ z, const float* __restrict__ emb) {
    __shared__ float  tile[64][65];
    __shared__ double sq[4][64];
    const int tid = threadIdx.x;

    if (blockIdx.x < 1024) {
        // ---- z role: (x,y,b) = (t-block, d-block, batch) ----
        const int x = blockIdx.x & 31, y = (blockIdx.x >> 5) & 3, b = blockIdx.x >> 7;
        const int d0 = y * 64, t0 = x * 64;
        const int tx = tid & 63, ty = tid >> 6;

        for (int r = ty; r < 64; r += 4)
            tile[r][tx] = z[((size_t)b * DD + d0 + r) * TT + t0 + tx];
        __syncthreads();

        // ssq partial: thread (q, tl) sums d-local [q*16, q*16+16) for token tl
        {
            const int tl = tid & 63, q = tid >> 6;
            double s = 0.0;
#pragma unroll
            for (int dl = 0; dl < 16; dl++) {
                float v = tile[q * 16 + dl][tl];
                s += (double)v * v;
            }
            sq[q][tl] = s;
        }
        __syncthreads();
        if (tid < 64) {
            double tot = ((sq[0][tid] + sq[1][tid]) + sq[2][tid]) + sq[3][tid];
            g_Ap[y][b * TT + t0 + tid] = tot;
        }
        // splits (reads tile only; no race with sq/g_Ap writes above)
        for (int r = ty; r < 64; r += 4) {
            size_t m = (size_t)b * TT + t0 + r;
            float v = tile[tx][r];
            __half h = __float2half(v);
            g_Zh[m * DD + d0 + tx] = h;
            g_Zl[m * DD + d0 + tx] = __float2half((v - __half2float(h)) * LO_SCALE);
        }
    } else {
        // ---- emb role: one warp per code row ----
        const int row  = (blockIdx.x - 1024) * 8 + (tid >> 5);
        const int lane = tid & 31;
        const float* p = emb + (size_t)row * DD;
        double s = 0.0;
#pragma unroll
        for (int it = 0; it < 8; it++) {
            int d = it * 32 + lane;
            float v = p[d];
            __half h = __float2half(v);
            g_Eh[(size_t)row * DD + d] = h;
            g_El[(size_t)row * DD + d] = __float2half((v - __half2float(h)) * LO_SCALE);
            s += (double)v * v;
        }
#pragma unroll
        for (int off = 16; off; off >>= 1) s += __shfl_down_sync(0xffffffffu, s, off);
        if (lane == 0) g_Bsq[row] = (float)s;
    }
}

// ---------------------------------------------------------------------------
// Persistent GEMM + fused argmin (inner loop unchanged from R8).
__global__ void __launch_bounds__(256, 1)
k_mma() {
    extern __shared__ char smem_raw[];
    const uint32_t raw = smem_u32(smem_raw);
    const uint32_t sb  = (raw + 1023) & ~1023u;

    const int tid  = threadIdx.x;
    const int wid  = tid >> 5, lane = tid & 31;
    const int wm   = wid >> 2, wn   = wid & 3;

    const int u0 = (int)(((long long)blockIdx.x * NUNITS) / NCTA);
    const int u1 = (int)(((long long)(blockIdx.x + 1) * NUNITS) / NCTA);

#define ISSUE_B(J, STAGE, NBASE) do {                                         \
    int _tg = (NBASE) + ((J) >> 2), _c = (J) & 3;                             \
    _Pragma("unroll")                                                         \
    for (int _h = 0; _h < 2; _h++) {                                          \
        const __half* _src = (_h ? g_El : g_Eh)                               \
                           + (size_t)(_tg * NTILE) * DD + _c * KCH;           \
        _Pragma("unroll")                                                     \
        for (int _j = 0; _j < 4; _j++) {                                      \
            int _seg = tid + _j * 256;                                        \
            int _row = _seg >> 3, _sg = _seg & 7;                             \
            cp16(addrB(sb, (STAGE), _h, _row, _sg * 8),                       \
                 _src + (size_t)_row * DD + _sg * 8);                         \
        }                                                                     \
    }                                                                         \
} while (0)

    int prev_tile = -1;
    for (int u = u0; u < u1; u++) {
        const int tile0 = u >> 3;
        const int nbase = (u & 7) * 8;
        const int t0g   = tile0 * MT;

        if (tile0 != prev_tile) {
            prev_tile = tile0;
#pragma unroll
            for (int si = 0; si < 2; si++) {
                const __half* src = (si ? g_Zl : g_Zh) + (size_t)t0g * DD;
#pragma unroll
                for (int j = 0; j < 16; j++) {
                    int seg = tid + j * 256;
                    int row = seg >> 5, sg = seg & 31;
                    cp16(sb + si * 65536 + row * 512 + ((sg * 16) ^ ((row & 7) << 4)),
                         src + (size_t)row * DD + sg * 8);
                }
            }
        }
        ISSUE_B(0, 0, nbase);
        cp_commit();
        ISSUE_B(1, 1, nbase);
        cp_commit();

        float av[8];
#pragma unroll
        for (int mt = 0; mt < 4; mt++) {
            int r0 = t0g + wm * 64 + mt * 16 + (lane >> 2);
            av[mt * 2] = (float)(((g_Ap[0][r0] + g_Ap[1][r0])
                                 + g_Ap[2][r0]) + g_Ap[3][r0]);
            av[mt * 2 + 1] = (float)(((g_Ap[0][r0 + 8] + g_Ap[1][r0 + 8])
                                     + g_Ap[2][r0 + 8]) + g_Ap[3][r0 + 8]);
        }
        float bestd[8]; int besti[8];
#pragma unroll
        for (int k = 0; k < 8; k++) { bestd[k] = CUDART_INF_F; besti[k] = 0; }

        float acc0[4][4][4], acc1[4][4][4];

        for (int j = 0; j < 32; j++) {
            const int stage = j % NSTAGE;
            if (j < 31) cp_wait<1>(); else cp_wait<0>();
            __syncthreads();
            if (j + 2 < 32) { ISSUE_B(j + 2, (j + 2) % NSTAGE, nbase); cp_commit(); }

            const int tileg = nbase + (j >> 2), c = j & 3;
            if (c == 0) {
#pragma unroll
                for (int mt = 0; mt < 4; mt++)
#pragma unroll
                    for (int nt = 0; nt < 4; nt++)
#pragma unroll
                        for (int q = 0; q < 4; q++) {
                            acc0[mt][nt][q] = 0.0f; acc1[mt][nt][q] = 0.0f;
                        }
            }
#pragma unroll
            for (int k16 = 0; k16 < 4; k16++) {
                const int kloc  = k16 * 16;
                const int kglob = c * KCH + kloc;
                uint32_t ah[4][4], al[4][4], beh[4][2], bel[4][2];

#pragma unroll
                for (int ntp = 0; ntp < 2; ntp++) {
                    const int g   = lane >> 3;
                    const int row = wn * 32 + ntp * 16 + ((g >> 1) << 3) + (lane & 7);
                    const int col = kloc + ((g & 1) << 3);
                    uint32_t r4[4];
                    ldsm4(r4, addrB(sb, stage, 0, row, col));
                    beh[ntp * 2][0] = r4[0]; beh[ntp * 2][1] = r4[1];
                    beh[ntp * 2 + 1][0] = r4[2]; beh[ntp * 2 + 1][1] = r4[3];
                }
#pragma unroll
                for (int mt = 0; mt < 4; mt++) {
                    const int row = wm * 64 + mt * 16 + (lane & 15);
                    const int col = kglob + ((lane >> 4) << 3);
                    ldsm4(ah[mt], addrA(sb, 0, row, col));
                }
#pragma unroll
                for (int mt = 0; mt < 4; mt++)
#pragma unroll
                    for (int nt = 0; nt < 4; nt++)
                        mma16816(acc0[mt][nt], ah[mt], beh[nt]);

#pragma unroll
                for (int ntp = 0; ntp < 2; ntp++) {
                    const int g   = lane >> 3;
                    const int row = wn * 32 + ntp * 16 + ((g >> 1) << 3) + (lane & 7);
                    const int col = kloc + ((g & 1) << 3);
                    uint32_t r4[4];
                    ldsm4(r4, addrB(sb, stage, 1, row, col));
                    bel[ntp * 2][0] = r4[0]; bel[ntp * 2][1] = r4[1];
                    bel[ntp * 2 + 1][0] = r4[2]; bel[ntp * 2 + 1][1] = r4[3];
                }
#pragma unroll
                for (int mt = 0; mt < 4; mt++) {
                    const int row = wm * 64 + mt * 16 + (lane & 15);
                    const int col = kglob + ((lane >> 4) << 3);
                    ldsm4(al[mt], addrA(sb, 1, row, col));
                }
#pragma unroll
                for (int mt = 0; mt < 4; mt++)
#pragma unroll
                    for (int nt = 0; nt < 4; nt++)
                        mma16816(acc1[mt][nt], ah[mt], bel[nt]);
#pragma unroll
                for (int mt = 0; mt < 4; mt++)
#pragma unroll
                    for (int nt = 0; nt < 4; nt++)
                        mma16816(acc1[mt][nt], al[mt], beh[nt]);
            }

            if (c == 3) {
                const int nb = tileg * NTILE + wn * 32 + (lane & 3) * 2;
#pragma unroll
                for (int nt = 0; nt < 4; nt++) {
                    const int n0 = nb + nt * 8;
                    const float bq0 = __ldg(&g_Bsq[n0]);
                    const float bq1 = __ldg(&g_Bsq[n0 + 1]);
#pragma unroll
                    for (int mt = 0; mt < 4; mt++) {
                        const float a00 = acc0[mt][nt][0] + acc1[mt][nt][0] * LO_UNSCALE;
                        const float a01 = acc0[mt][nt][1] + acc1[mt][nt][1] * LO_UNSCALE;
                        const float a10 = acc0[mt][nt][2] + acc1[mt][nt][2] * LO_UNSCALE;
                        const float a11 = acc0[mt][nt][3] + acc1[mt][nt][3] * LO_UNSCALE;
                        const int r0 = mt * 2, r1 = mt * 2 + 1;
                        float d;
                        d = fmaf(-2.0f, a00, av[r0] + bq0);
                        if (d < bestd[r0]) { bestd[r0] = d; besti[r0] = n0; }
                        d = fmaf(-2.0f, a01, av[r0] + bq1);
                        if (d < bestd[r0]) { bestd[r0] = d; besti[r0] = n0 + 1; }
                        d = fmaf(-2.0f, a10, av[r1] + bq0);
                        if (d < bestd[r1]) { bestd[r1] = d; besti[r1] = n0; }
                        d = fmaf(-2.0f, a11, av[r1] + bq1);
                        if (d < bestd[r1]) { bestd[r1] = d; besti[r1] = n0 + 1; }
                    }
                }
            }
        }

        __syncthreads();

#pragma unroll
        for (int k = 0; k < 8; k++) {
#pragma unroll
            for (int off = 1; off <= 2; off <<= 1) {
                float od = __shfl_xor_sync(0xffffffffu, bestd[k], off);
                int   oi = __shfl_xor_sync(0xffffffffu, besti[k], off);
                if (od < bestd[k] || (od == bestd[k] && oi < besti[k])) {
                    bestd[k] = od; besti[k] = oi;
                }
            }
        }
        if ((lane & 3) == 0) {
            const size_t xo = (size_t)((u & 7) * 4 + wn) * MTOK + t0g;
#pragma unroll
            for (int k = 0; k < 8; k++) {
                const int mt = k >> 1, h = k & 1;
                const int row = wm * 64 + mt * 16 + (lane >> 2) + h * 8;
                g_pd[xo + row] = bestd[k];
                g_pi[xo + row] = besti[k];
            }
        }
    }
#undef ISSUE_B
}

// ---------------------------------------------------------------------------
// Fused merge + gather + STE + loss. Block = 64 tokens.
__global__ void __launch_bounds__(256)
k_gather(const float* __restrict__ z,
         const float* __restrict__ emb,
         float* __restrict__ out) {
    __shared__ float erow[64 * 257];
    __shared__ int   codes[64];
    __shared__ double red[256];

    const int tid = threadIdx.x;
    const int m0  = blockIdx.x * 64;
    const int b   = m0 >> 11;
    const int t0  = m0 & 2047;

    if (tid < 64) {
        const int m = m0 + tid;
        float bd = g_pd[m]; int bi = g_pi[m];
#pragma unroll
        for (int x = 1; x < 32; x++) {
            float d2 = g_pd[(size_t)x * MTOK + m];
            int   i2 = g_pi[(size_t)x * MTOK + m];
            if (d2 < bd || (d2 == bd && i2 < bi)) { bd = d2; bi = i2; }
        }
        codes[tid] = bi;
        out[BDT + 1 + m] = (float)bi;
    }
    __syncthreads();

#pragma unroll
    for (int it = 0; it < 64; it++) {
        int idx = it * 256 + tid;
        int row = idx >> 8, col = idx & 255;
        erow[row * 257 + col] = emb[(size_t)codes[row] * DD + col];
    }
    __syncthreads();

    const float* zb = z   + ((size_t)b * DD) * TT + t0;
    float*       ob = out + ((size_t)b * DD) * TT + t0;
    double ls = 0.0;
#pragma unroll 4
    for (int it = 0; it < 64; it++) {
        int idx = it * 256 + tid;
        int d = idx >> 6, tt = idx & 63;
        float zp = zb[(size_t)d * TT + tt];
        float zq = erow[tt * 257 + d];
        float diff = zq - zp;
        ob[(size_t)d * TT + tt] = zp + diff;
        ls += (double)(diff * diff);
    }
    red[tid] = ls;
    __syncthreads();
#pragma unroll
    for (int s = 128; s; s >>= 1) {
        if (tid < s) red[tid] += red[tid + s];
        __syncthreads();
    }
    if (tid == 0) g_part[blockIdx.x] = red[0];
}

__global__ void k_final(float* __restrict__ out) {
    __shared__ double red[256];
    double s = (threadIdx.x < GATHER_BLOCKS) ? g_part[threadIdx.x] : 0.0;
    red[threadIdx.x] = s;
    __syncthreads();
#pragma unroll
    for (int st = 128; st; st >>= 1) {
        if (threadIdx.x < st) red[threadIdx.x] += red[threadIdx.x + st];
        __syncthreads();
    }
    if (threadIdx.x == 0) out[BDT] = (float)(1.25 * red[0] / (double)BDT);
}

// ---------------------------------------------------------------------------
extern "C" void kernel_launch(void* const* d_in, const int* in_sizes, int n_in,
                              void* d_out, int out_size) {
    const float* z   = (const float*)d_in[0];
    const float* emb = (const float*)d_in[1];
    float* out = (float*)d_out;

    cudaFuncSetAttribute(k_mma, cudaFuncAttributeMaxDynamicSharedMemorySize, DYN_SMEM);

    k_prep<<<2048, 256>>>(z, emb);
    k_mma<<<NCTA, 256, DYN_SMEM>>>();
    k_gather<<<GATHER_BLOCKS, 256>>>(z, emb, out);
    k_final<<<1, 256>>>(out);
}

// round 10
// speedup vs baseline: 1.0696x; 1.0007x over previous
#include <cuda_runtime.h>
#include <cuda_fp16.h>
#include <cstdint>
#include <math_constants.h>

// ---------------------------------------------------------------------------
#define BB   8
#define DD   256
#define TT   2048
#define NE   8192
#define MTOK (BB * TT)        // 16384
#define BDT  (BB * DD * TT)   // 4194304

#define MT    128             // tokens per tile
#define NTILE 128             // codes per N-tile
#define NBLK  8               // n-blocks per token tile (1024 codes each)
#define NUNITS (MTOK / MT * NBLK)   // 1024 work units
#define NCTA  148
#define KCH   64

#define GATHER_BLOCKS 256     // 64 tokens per block
#define LO_SCALE   4096.0f
#define LO_UNSCALE 2.44140625e-4f    // 2^-12

// ---------------------------------------------------------------------------
__device__ double g_Ap[4][MTOK];      // ||z||^2 quad partials (fp64, fixed order)
__device__ float  g_Bsq[NE];
__device__ double g_part[GATHER_BLOCKS];
__device__ unsigned int g_done = 0;   // gather completion ticket (self-resetting)
__device__ __half g_Zh[(size_t)MTOK * DD];
__device__ __half g_Zl[(size_t)MTOK * DD];
__device__ __half g_Eh[(size_t)NE * DD];
__device__ __half g_El[(size_t)NE * DD];
// partials transposed: [x][m], x = nblk*4 + wn  (coalesced write AND read)
__device__ float  g_pd[32 * (size_t)MTOK];
__device__ int    g_pi[32 * (size_t)MTOK];

// ---------------------------------------------------------------------------
__device__ __forceinline__ uint32_t smem_u32(const void* p) {
    uint32_t a;
    asm("{ .reg .u64 t; cvta.to.shared.u64 t, %1; cvt.u32.u64 %0, t; }"
        : "=r"(a) : "l"(p));
    return a;
}
__device__ __forceinline__ void cp16(uint32_t dst, const void* src) {
    asm volatile("cp.async.cg.shared.global [%0], [%1], 16;" :: "r"(dst), "l"(src));
}
__device__ __forceinline__ void cp_commit() {
    asm volatile("cp.async.commit_group;" ::: "memory");
}
template <int N>
__device__ __forceinline__ void cp_wait() {
    asm volatile("cp.async.wait_group %0;" :: "n"(N) : "memory");
}
__device__ __forceinline__ void ldsm4(uint32_t* r, uint32_t a) {
    asm volatile("ldmatrix.sync.aligned.m8n8.x4.shared.b16 {%0,%1,%2,%3}, [%4];"
        : "=r"(r[0]), "=r"(r[1]), "=r"(r[2]), "=r"(r[3]) : "r"(a));
}
__device__ __forceinline__ void mma16816(float* d, const uint32_t* a, const uint32_t* b) {
    asm volatile("mma.sync.aligned.m16n8k16.row.col.f32.f16.f16.f32 "
        "{%0,%1,%2,%3}, {%4,%5,%6,%7}, {%8,%9}, {%0,%1,%2,%3};"
        : "+f"(d[0]), "+f"(d[1]), "+f"(d[2]), "+f"(d[3])
        : "r"(a[0]), "r"(a[1]), "r"(a[2]), "r"(a[3]), "r"(b[0]), "r"(b[1]));
}

// smem: A zh [0,64K) zl [64K,128K); B 3 stages x (eh 16K + el 16K) at OFF_B
#define OFF_B   131072
#define NSTAGE  3
#define DYN_SMEM (1024 + OFF_B + NSTAGE * 32768)

__device__ __forceinline__ uint32_t addrA(uint32_t sb, int split, int row, int k) {
    return sb + split * 65536 + row * 512 + ((k * 2) ^ ((row & 7) << 4));
}
__device__ __forceinline__ uint32_t addrB(uint32_t sb, int stage, int half, int row, int k) {
    return sb + OFF_B + stage * 32768 + half * 16384 + row * 128
         + ((k * 2) ^ ((row & 7) << 4));
}

// ---------------------------------------------------------------------------
// Fused prep: blocks [0,1024) transpose+split z AND compute ||z||^2 partials;
// blocks [1024,2048) split emb + compute ||e||^2. half2-wide split stores.
__global__ void __launch_bounds__(256)
k_prep(const float* __restrict__ z, const float* __restrict__ emb) {
    __shared__ float  tile[64][65];
    __shared__ double sq[4][64];
    const int tid = threadIdx.x;

    if (blockIdx.x < 1024) {
        // ---- z role: (x,y,b) = (t-block, d-block, batch) ----
        const int x = blockIdx.x & 31, y = (blockIdx.x >> 5) & 3, b = blockIdx.x >> 7;
        const int d0 = y * 64, t0 = x * 64;
        const int tx = tid & 63, ty = tid >> 6;

        for (int r = ty; r < 64; r += 4)
            tile[r][tx] = z[((size_t)b * DD + d0 + r) * TT + t0 + tx];
        __syncthreads();

        // ssq partial: thread (q, tl) sums d-local [q*16, q*16+16) for token tl
        {
            const int tl = tid & 63, q = tid >> 6;
            double s = 0.0;
#pragma unroll
            for (int dl = 0; dl < 16; dl++) {
                float v = tile[q * 16 + dl][tl];
                s += (double)v * v;
            }
            sq[q][tl] = s;
        }
        __syncthreads();
        if (tid < 64) {
            double tot = ((sq[0][tid] + sq[1][tid]) + sq[2][tid]) + sq[3][tid];
            g_Ap[y][b * TT + t0 + tid] = tot;
        }
        // splits: half2 stores (thread owns d-pair 2*tx2, token row r)
        {
            const int tx2 = tid & 31, ty2 = tid >> 5;
#pragma unroll
            for (int r = ty2; r < 64; r += 8) {
                size_t m = (size_t)b * TT + t0 + r;
                float v0 = tile[2 * tx2][r], v1 = tile[2 * tx2 + 1][r];
                __half h0 = __float2half(v0), h1 = __float2half(v1);
                __half l0 = __float2half((v0 - __half2float(h0)) * LO_SCALE);
                __half l1 = __float2half((v1 - __half2float(h1)) * LO_SCALE);
                *(__half2*)&g_Zh[m * DD + d0 + 2 * tx2] = __halves2half2(h0, h1);
                *(__half2*)&g_Zl[m * DD + d0 + 2 * tx2] = __halves2half2(l0, l1);
            }
        }
    } else {
        // ---- emb role: one warp per code row, float2/half2-wide ----
        const int row  = (blockIdx.x - 1024) * 8 + (tid >> 5);
        const int lane = tid & 31;
        const float* p = emb + (size_t)row * DD;
        double s = 0.0;
#pragma unroll
        for (int it = 0; it < 4; it++) {
            int d = it * 64 + 2 * lane;
            float2 v = *(const float2*)(p + d);
            __half h0 = __float2half(v.x), h1 = __float2half(v.y);
            __half l0 = __float2half((v.x - __half2float(h0)) * LO_SCALE);
            __half l1 = __float2half((v.y - __half2float(h1)) * LO_SCALE);
            *(__half2*)&g_Eh[(size_t)row * DD + d] = __halves2half2(h0, h1);
            *(__half2*)&g_El[(size_t)row * DD + d] = __halves2half2(l0, l1);
            s += (double)v.x * v.x + (double)v.y * v.y;
        }
#pragma unroll
        for (int off = 16; off; off >>= 1) s += __shfl_down_sync(0xffffffffu, s, off);
        if (lane == 0) g_Bsq[row] = (float)s;
    }
}

// ---------------------------------------------------------------------------
// Persistent GEMM + fused argmin (inner loop unchanged — at its ceiling).
__global__ void __launch_bounds__(256, 1)
k_mma() {
    extern __shared__ char smem_raw[];
    const uint32_t raw = smem_u32(smem_raw);
    const uint32_t sb  = (raw + 1023) & ~1023u;

    const int tid  = threadIdx.x;
    const int wid  = tid >> 5, lane = tid & 31;
    const int wm   = wid >> 2, wn   = wid & 3;

    const int u0 = (int)(((long long)blockIdx.x * NUNITS) / NCTA);
    const int u1 = (int)(((long long)(blockIdx.x + 1) * NUNITS) / NCTA);

#define ISSUE_B(J, STAGE, NBASE) do {                                         \
    int _tg = (NBASE) + ((J) >> 2), _c = (J) & 3;                             \
    _Pragma("unroll")                                                         \
    for (int _h = 0; _h < 2; _h++) {                                          \
        const __half* _src = (_h ? g_El : g_Eh)                               \
                           + (size_t)(_tg * NTILE) * DD + _c * KCH;           \
        _Pragma("unroll")                                                     \
        for (int _j = 0; _j < 4; _j++) {                                      \
            int _seg = tid + _j * 256;                                        \
            int _row = _seg >> 3, _sg = _seg & 7;                             \
            cp16(addrB(sb, (STAGE), _h, _row, _sg * 8),                       \
                 _src + (size_t)_row * DD + _sg * 8);                         \
        }                                                                     \
    }                                                                         \
} while (0)

    int prev_tile = -1;
    for (int u = u0; u < u1; u++) {
        const int tile0 = u >> 3;
        const int nbase = (u & 7) * 8;
        const int t0g   = tile0 * MT;

        if (tile0 != prev_tile) {
            prev_tile = tile0;
#pragma unroll
            for (int si = 0; si < 2; si++) {
                const __half* src = (si ? g_Zl : g_Zh) + (size_t)t0g * DD;
#pragma unroll
                for (int j = 0; j < 16; j++) {
                    int seg = tid + j * 256;
                    int row = seg >> 5, sg = seg & 31;
                    cp16(sb + si * 65536 + row * 512 + ((sg * 16) ^ ((row & 7) << 4)),
                         src + (size_t)row * DD + sg * 8);
                }
            }
        }
        ISSUE_B(0, 0, nbase);
        cp_commit();
        ISSUE_B(1, 1, nbase);
        cp_commit();

        float av[8];
#pragma unroll
        for (int mt = 0; mt < 4; mt++) {
            int r0 = t0g + wm * 64 + mt * 16 + (lane >> 2);
            av[mt * 2] = (float)(((g_Ap[0][r0] + g_Ap[1][r0])
                                 + g_Ap[2][r0]) + g_Ap[3][r0]);
            av[mt * 2 + 1] = (float)(((g_Ap[0][r0 + 8] + g_Ap[1][r0 + 8])
                                     + g_Ap[2][r0 + 8]) + g_Ap[3][r0 + 8]);
        }
        float bestd[8]; int besti[8];
#pragma unroll
        for (int k = 0; k < 8; k++) { bestd[k] = CUDART_INF_F; besti[k] = 0; }

        float acc0[4][4][4], acc1[4][4][4];

        for (int j = 0; j < 32; j++) {
            const int stage = j % NSTAGE;
            if (j < 31) cp_wait<1>(); else cp_wait<0>();
            __syncthreads();
            if (j + 2 < 32) { ISSUE_B(j + 2, (j + 2) % NSTAGE, nbase); cp_commit(); }

            const int tileg = nbase + (j >> 2), c = j & 3;
            if (c == 0) {
#pragma unroll
                for (int mt = 0; mt < 4; mt++)
#pragma unroll
                    for (int nt = 0; nt < 4; nt++)
#pragma unroll
                        for (int q = 0; q < 4; q++) {
                            acc0[mt][nt][q] = 0.0f; acc1[mt][nt][q] = 0.0f;
                        }
            }
#pragma unroll
            for (int k16 = 0; k16 < 4; k16++) {
                const int kloc  = k16 * 16;
                const int kglob = c * KCH + kloc;
                uint32_t ah[4][4], al[4][4], beh[4][2], bel[4][2];

#pragma unroll
                for (int ntp = 0; ntp < 2; ntp++) {
                    const int g   = lane >> 3;
                    const int row = wn * 32 + ntp * 16 + ((g >> 1) << 3) + (lane & 7);
                    const int col = kloc + ((g & 1) << 3);
                    uint32_t r4[4];
                    ldsm4(r4, addrB(sb, stage, 0, row, col));
                    beh[ntp * 2][0] = r4[0]; beh[ntp * 2][1] = r4[1];
                    beh[ntp * 2 + 1][0] = r4[2]; beh[ntp * 2 + 1][1] = r4[3];
                }
#pragma unroll
                for (int mt = 0; mt < 4; mt++) {
                    const int row = wm * 64 + mt * 16 + (lane & 15);
                    const int col = kglob + ((lane >> 4) << 3);
                    ldsm4(ah[mt], addrA(sb, 0, row, col));
                }
#pragma unroll
                for (int mt = 0; mt < 4; mt++)
#pragma unroll
                    for (int nt = 0; nt < 4; nt++)
                        mma16816(acc0[mt][nt], ah[mt], beh[nt]);

#pragma unroll
                for (int ntp = 0; ntp < 2; ntp++) {
                    const int g   = lane >> 3;
                    const int row = wn * 32 + ntp * 16 + ((g >> 1) << 3) + (lane & 7);
                    const int col = kloc + ((g & 1) << 3);
                    uint32_t r4[4];
                    ldsm4(r4, addrB(sb, stage, 1, row, col));
                    bel[ntp * 2][0] = r4[0]; bel[ntp * 2][1] = r4[1];
                    bel[ntp * 2 + 1][0] = r4[2]; bel[ntp * 2 + 1][1] = r4[3];
                }
#pragma unroll
                for (int mt = 0; mt < 4; mt++) {
                    const int row = wm * 64 + mt * 16 + (lane & 15);
                    const int col = kglob + ((lane >> 4) << 3);
                    ldsm4(al[mt], addrA(sb, 1, row, col));
                }
#pragma unroll
                for (int mt = 0; mt < 4; mt++)
#pragma unroll
                    for (int nt = 0; nt < 4; nt++)
                        mma16816(acc1[mt][nt], ah[mt], bel[nt]);
#pragma unroll
                for (int mt = 0; mt < 4; mt++)
#pragma unroll
                    for (int nt = 0; nt < 4; nt++)
                        mma16816(acc1[mt][nt], al[mt], beh[nt]);
            }

            if (c == 3) {
                const int nb = tileg * NTILE + wn * 32 + (lane & 3) * 2;
#pragma unroll
                for (int nt = 0; nt < 4; nt++) {
                    const int n0 = nb + nt * 8;
                    const float bq0 = __ldg(&g_Bsq[n0]);
                    const float bq1 = __ldg(&g_Bsq[n0 + 1]);
#pragma unroll
                    for (int mt = 0; mt < 4; mt++) {
                        const float a00 = acc0[mt][nt][0] + acc1[mt][nt][0] * LO_UNSCALE;
                        const float a01 = acc0[mt][nt][1] + acc1[mt][nt][1] * LO_UNSCALE;
                        const float a10 = acc0[mt][nt][2] + acc1[mt][nt][2] * LO_UNSCALE;
                        const float a11 = acc0[mt][nt][3] + acc1[mt][nt][3] * LO_UNSCALE;
                        const int r0 = mt * 2, r1 = mt * 2 + 1;
                        float d;
                        d = fmaf(-2.0f, a00, av[r0] + bq0);
                        if (d < bestd[r0]) { bestd[r0] = d; besti[r0] = n0; }
                        d = fmaf(-2.0f, a01, av[r0] + bq1);
                        if (d < bestd[r0]) { bestd[r0] = d; besti[r0] = n0 + 1; }
                        d = fmaf(-2.0f, a10, av[r1] + bq0);
                        if (d < bestd[r1]) { bestd[r1] = d; besti[r1] = n0; }
                        d = fmaf(-2.0f, a11, av[r1] + bq1);
                        if (d < bestd[r1]) { bestd[r1] = d; besti[r1] = n0 + 1; }
                    }
                }
            }
        }

        __syncthreads();

#pragma unroll
        for (int k = 0; k < 8; k++) {
#pragma unroll
            for (int off = 1; off <= 2; off <<= 1) {
                float od = __shfl_xor_sync(0xffffffffu, bestd[k], off);
                int   oi = __shfl_xor_sync(0xffffffffu, besti[k], off);
                if (od < bestd[k] || (od == bestd[k] && oi < besti[k])) {
                    bestd[k] = od; besti[k] = oi;
                }
            }
        }
        if ((lane & 3) == 0) {
            const size_t xo = (size_t)((u & 7) * 4 + wn) * MTOK + t0g;
#pragma unroll
            for (int k = 0; k < 8; k++) {
                const int mt = k >> 1, h = k & 1;
                const int row = wm * 64 + mt * 16 + (lane >> 2) + h * 8;
                g_pd[xo + row] = bestd[k];
                g_pi[xo + row] = besti[k];
            }
        }
    }
#undef ISSUE_B
}

// ---------------------------------------------------------------------------
// Fused merge + gather + STE + loss + final reduce (last block, deterministic).
__global__ void __launch_bounds__(256)
k_gather(const float* __restrict__ z,
         const float* __restrict__ emb,
         float* __restrict__ out) {
    __shared__ float erow[64 * 257];
    __shared__ int   codes[64];
    __shared__ double red[256];
    __shared__ int   is_last;

    const int tid = threadIdx.x;
    const int m0  = blockIdx.x * 64;
    const int b   = m0 >> 11;
    const int t0  = m0 & 2047;

    // merge 32 partials per token (coalesced)
    if (tid < 64) {
        const int m = m0 + tid;
        float bd = g_pd[m]; int bi = g_pi[m];
#pragma unroll
        for (int x = 1; x < 32; x++) {
            float d2 = g_pd[(size_t)x * MTOK + m];
            int   i2 = g_pi[(size_t)x * MTOK + m];
            if (d2 < bd || (d2 == bd && i2 < bi)) { bd = d2; bi = i2; }
        }
        codes[tid] = bi;
        out[BDT + 1 + m] = (float)bi;
    }
    __syncthreads();

    // stage 64 emb rows (coalesced 1KB rows, padded conflict-free)
#pragma unroll
    for (int it = 0; it < 64; it++) {
        int idx = it * 256 + tid;
        int row = idx >> 8, col = idx & 255;
        erow[row * 257 + col] = emb[(size_t)codes[row] * DD + col];
    }
    __syncthreads();

    const float* zb = z   + ((size_t)b * DD) * TT + t0;
    float*       ob = out + ((size_t)b * DD) * TT + t0;
    double ls = 0.0;
    // float4 over the 64x256 tile: idx -> d = idx>>4, tt0 = (idx&15)*4
#pragma unroll 4
    for (int it = 0; it < 16; it++) {
        int idx = it * 256 + tid;
        int d = idx >> 4, tt0 = (idx & 15) * 4;
        float4 zp = *(const float4*)(zb + (size_t)d * TT + tt0);
        float q0 = erow[(tt0 + 0) * 257 + d];
        float q1 = erow[(tt0 + 1) * 257 + d];
        float q2 = erow[(tt0 + 2) * 257 + d];
        float q3 = erow[(tt0 + 3) * 257 + d];
        float d0 = q0 - zp.x, d1 = q1 - zp.y, d2 = q2 - zp.z, d3 = q3 - zp.w;
        float4 o;
        o.x = zp.x + d0; o.y = zp.y + d1; o.z = zp.z + d2; o.w = zp.w + d3;
        *(float4*)(ob + (size_t)d * TT + tt0) = o;
        ls += (double)(d0 * d0) + (double)(d1 * d1)
            + (double)(d2 * d2) + (double)(d3 * d3);
    }
    red[tid] = ls;
    __syncthreads();
#pragma unroll
    for (int s = 128; s; s >>= 1) {
        if (tid < s) red[tid] += red[tid + s];
        __syncthreads();
    }
    if (tid == 0) {
        g_part[blockIdx.x] = red[0];
        __threadfence();
        unsigned int t = atomicAdd(&g_done, 1u);
        is_last = (t == GATHER_BLOCKS - 1);
    }
    __syncthreads();

    // last block: deterministic fixed-order tree over g_part (bit-identical
    // to the old k_final regardless of block completion order)
    if (is_last) {
        double s = g_part[tid];
        __syncthreads();
        red[tid] = s;
        __syncthreads();
#pragma unroll
        for (int st = 128; st; st >>= 1) {
            if (tid < st) red[tid] += red[tid + st];
            __syncthreads();
        }
        if (tid == 0) {
            out[BDT] = (float)(1.25 * red[0] / (double)BDT);
            g_done = 0;                  // reset for next graph replay
        }
    }
}

// ---------------------------------------------------------------------------
extern "C" void kernel_launch(void* const* d_in, const int* in_sizes, int n_in,
                              void* d_out, int out_size) {
    const float* z   = (const float*)d_in[0];
    const float* emb = (const float*)d_in[1];
    float* out = (float*)d_out;

    cudaFuncSetAttribute(k_mma, cudaFuncAttributeMaxDynamicSharedMemorySize, DYN_SMEM);

    k_prep<<<2048, 256>>>(z, emb);
    k_mma<<<NCTA, 256, DYN_SMEM>>>();
    k_gather<<<GATHER_BLOCKS, 256>>>(z, emb, out);
}

// round 13
// speedup vs baseline: 1.0745x; 1.0046x over previous
#include <cuda_runtime.h>
#include <cuda_fp16.h>
#include <cstdint>
#include <math_constants.h>

// ---------------------------------------------------------------------------
#define BB   8
#define DD   256
#define TT   2048
#define NE   8192
#define MTOK (BB * TT)        // 16384
#define BDT  (BB * DD * TT)   // 4194304

#define MT    128             // tokens per tile
#define NTILE 128             // codes per N-tile
#define NBLK  8               // n-blocks per token tile (1024 codes each)
#define NUNITS (MTOK / MT * NBLK)   // 1024 work units
#define NCTA  148
#define KCH   64

#define GATHER_BLOCKS 2048
#define LO_SCALE   4096.0f
#define LO_UNSCALE 2.44140625e-4f    // 2^-12

// ---------------------------------------------------------------------------
// NUMERICS NOTE: d-values are degenerate (spread ~2e-3 around ||z||^2~256 vs
// ulp(256)=3e-5) — argmin is decided by first-index tie-break inside the
// lowest fp32 rounding cell, so av/bq must be computed exactly as proven in
// R10: per-64d-slice fp64 partial in g_Ap[y][m], summed in fixed order.
// R11/R12 failed from a write-race (every y-block wrote all 4 slots).
__device__ double g_Ap[4][MTOK];      // ||z||^2 64d-slice partials (fp64)
__device__ float  g_Bsq[NE];
__device__ int    g_idx[MTOK];
__device__ double g_part[GATHER_BLOCKS];
__device__ unsigned int g_done = 0;   // gather ticket (self-resetting)
__device__ __half g_Zh[(size_t)MTOK * DD];
__device__ __half g_Zl[(size_t)MTOK * DD];
__device__ __half g_Eh[(size_t)NE * DD];
__device__ __half g_El[(size_t)NE * DD];
// partials transposed: [x][m], x = nblk*4 + wn
__device__ float  g_pd[32 * (size_t)MTOK];
__device__ int    g_pi[32 * (size_t)MTOK];

// ---------------------------------------------------------------------------
__device__ __forceinline__ uint32_t smem_u32(const void* p) {
    uint32_t a;
    asm("{ .reg .u64 t; cvta.to.shared.u64 t, %1; cvt.u32.u64 %0, t; }"
        : "=r"(a) : "l"(p));
    return a;
}
__device__ __forceinline__ void cp16(uint32_t dst, const void* src) {
    asm volatile("cp.async.cg.shared.global [%0], [%1], 16;" :: "r"(dst), "l"(src));
}
__device__ __forceinline__ void cp_commit() {
    asm volatile("cp.async.commit_group;" ::: "memory");
}
template <int N>
__device__ __forceinline__ void cp_wait() {
    asm volatile("cp.async.wait_group %0;" :: "n"(N) : "memory");
}
__device__ __forceinline__ void ldsm4(uint32_t* r, uint32_t a) {
    asm volatile("ldmatrix.sync.aligned.m8n8.x4.shared.b16 {%0,%1,%2,%3}, [%4];"
        : "=r"(r[0]), "=r"(r[1]), "=r"(r[2]), "=r"(r[3]) : "r"(a));
}
__device__ __forceinline__ void mma16816(float* d, const uint32_t* a, const uint32_t* b) {
    asm volatile("mma.sync.aligned.m16n8k16.row.col.f32.f16.f16.f32 "
        "{%0,%1,%2,%3}, {%4,%5,%6,%7}, {%8,%9}, {%0,%1,%2,%3};"
        : "+f"(d[0]), "+f"(d[1]), "+f"(d[2]), "+f"(d[3])
        : "r"(a[0]), "r"(a[1]), "r"(a[2]), "r"(a[3]), "r"(b[0]), "r"(b[1]));
}

#define OFF_B   131072
#define NSTAGE  3
#define DYN_SMEM (1024 + OFF_B + NSTAGE * 32768)

__device__ __forceinline__ uint32_t addrA(uint32_t sb, int split, int row, int k) {
    return sb + split * 65536 + row * 512 + ((k * 2) ^ ((row & 7) << 4));
}
__device__ __forceinline__ uint32_t addrB(uint32_t sb, int stage, int half, int row, int k) {
    return sb + OFF_B + stage * 32768 + half * 16384 + row * 128
         + ((k * 2) ^ ((row & 7) << 4));
}

// ---------------------------------------------------------------------------
// Fused prep (exact R10 semantics): z-role blocks transpose+split z + fp64 ssq
// slice-partials (g_Ap[y][m] = this block's 64-d total); emb-role blocks
// split emb + fp64 ||e||^2.
__global__ void __launch_bounds__(256)
k_prep(const float* __restrict__ z, const float* __restrict__ emb) {
    __shared__ float  tile[64][65];
    __shared__ double sq[4][64];
    const int tid = threadIdx.x;

    if (blockIdx.x < 1024) {
        const int x = blockIdx.x & 31, y = (blockIdx.x >> 5) & 3, b = blockIdx.x >> 7;
        const int d0 = y * 64, t0 = x * 64;
        const int tx = tid & 63, ty = tid >> 6;

        for (int r = ty; r < 64; r += 4)
            tile[r][tx] = z[((size_t)b * DD + d0 + r) * TT + t0 + tx];
        __syncthreads();

        {
            const int tl = tid & 63, q = tid >> 6;
            double s = 0.0;
#pragma unroll
            for (int dl = 0; dl < 16; dl++) {
                float v = tile[q * 16 + dl][tl];
                s += (double)v * v;
            }
            sq[q][tl] = s;
        }
        __syncthreads();
        if (tid < 64) {
            // R10-proven: THIS y-slice's 64-d total into slot y only.
            double tot = ((sq[0][tid] + sq[1][tid]) + sq[2][tid]) + sq[3][tid];
            g_Ap[y][b * TT + t0 + tid] = tot;
        }
        {
            const int tx2 = tid & 31, ty2 = tid >> 5;
#pragma unroll
            for (int r = ty2; r < 64; r += 8) {
                size_t m = (size_t)b * TT + t0 + r;
                float v0 = tile[2 * tx2][r], v1 = tile[2 * tx2 + 1][r];
                __half h0 = __float2half(v0), h1 = __float2half(v1);
                __half l0 = __float2half((v0 - __half2float(h0)) * LO_SCALE);
                __half l1 = __float2half((v1 - __half2float(h1)) * LO_SCALE);
                *(__half2*)&g_Zh[m * DD + d0 + 2 * tx2] = __halves2half2(h0, h1);
                *(__half2*)&g_Zl[m * DD + d0 + 2 * tx2] = __halves2half2(l0, l1);
            }
        }
    } else {
        const int row  = (blockIdx.x - 1024) * 8 + (tid >> 5);
        const int lane = tid & 31;
        const float* p = emb + (size_t)row * DD;
        double s = 0.0;
#pragma unroll
        for (int it = 0; it < 4; it++) {
            int d = it * 64 + 2 * lane;
            float2 v = *(const float2*)(p + d);
            __half h0 = __float2half(v.x), h1 = __float2half(v.y);
            __half l0 = __float2half((v.x - __half2float(h0)) * LO_SCALE);
            __half l1 = __float2half((v.y - __half2float(h1)) * LO_SCALE);
            *(__half2*)&g_Eh[(size_t)row * DD + d] = __halves2half2(h0, h1);
            *(__half2*)&g_El[(size_t)row * DD + d] = __halves2half2(l0, l1);
            s += (double)v.x * v.x + (double)v.y * v.y;
        }
#pragma unroll
        for (int off = 16; off; off >>= 1) s += __shfl_down_sync(0xffffffffu, s, off);
        if (lane == 0) g_Bsq[row] = (float)s;
    }
}

// ---------------------------------------------------------------------------
// Persistent GEMM + fused argmin (R10-proven, unchanged).
__global__ void __launch_bounds__(256, 1)
k_mma() {
    extern __shared__ char smem_raw[];
    const uint32_t raw = smem_u32(smem_raw);
    const uint32_t sb  = (raw + 1023) & ~1023u;

    const int tid  = threadIdx.x;
    const int wid  = tid >> 5, lane = tid & 31;
    const int wm   = wid >> 2, wn   = wid & 3;

    const int u0 = (int)(((long long)blockIdx.x * NUNITS) / NCTA);
    const int u1 = (int)(((long long)(blockIdx.x + 1) * NUNITS) / NCTA);

#define ISSUE_B(J, STAGE, NBASE) do {                                         \
    int _tg = (NBASE) + ((J) >> 2), _c = (J) & 3;                             \
    _Pragma("unroll")                                                         \
    for (int _h = 0; _h < 2; _h++) {                                          \
        const __half* _src = (_h ? g_El : g_Eh)                               \
                           + (size_t)(_tg * NTILE) * DD + _c * KCH;           \
        _Pragma("unroll")                                                     \
        for (int _j = 0; _j < 4; _j++) {                                      \
            int _seg = tid + _j * 256;                                        \
            int _row = _seg >> 3, _sg = _seg & 7;                             \
            cp16(addrB(sb, (STAGE), _h, _row, _sg * 8),                       \
                 _src + (size_t)_row * DD + _sg * 8);                         \
        }                                                                     \
    }                                                                         \
} while (0)

    int prev_tile = -1;
    for (int u = u0; u < u1; u++) {
        const int tile0 = u >> 3;
        const int nbase = (u & 7) * 8;
        const int t0g   = tile0 * MT;

        if (tile0 != prev_tile) {
            prev_tile = tile0;
#pragma unroll
            for (int si = 0; si < 2; si++) {
                const __half* src = (si ? g_Zl : g_Zh) + (size_t)t0g * DD;
#pragma unroll
                for (int j = 0; j < 16; j++) {
                    int seg = tid + j * 256;
                    int row = seg >> 5, sg = seg & 31;
                    cp16(sb + si * 65536 + row * 512 + ((sg * 16) ^ ((row & 7) << 4)),
                         src + (size_t)row * DD + sg * 8);
                }
            }
        }
        ISSUE_B(0, 0, nbase);
        cp_commit();
        ISSUE_B(1, 1, nbase);
        cp_commit();

        float av[8];
#pragma unroll
        for (int mt = 0; mt < 4; mt++) {
            int r0 = t0g + wm * 64 + mt * 16 + (lane >> 2);
            av[mt * 2] = (float)(((g_Ap[0][r0] + g_Ap[1][r0])
                                 + g_Ap[2][r0]) + g_Ap[3][r0]);
            av[mt * 2 + 1] = (float)(((g_Ap[0][r0 + 8] + g_Ap[1][r0 + 8])
                                     + g_Ap[2][r0 + 8]) + g_Ap[3][r0 + 8]);
        }
        float bestd[8]; int besti[8];
#pragma unroll
        for (int k = 0; k < 8; k++) { bestd[k] = CUDART_INF_F; besti[k] = 0; }

        float acc0[4][4][4], acc1[4][4][4];

        for (int j = 0; j < 32; j++) {
            const int stage = j % NSTAGE;
            if (j < 31) cp_wait<1>(); else cp_wait<0>();
            __syncthreads();
            if (j + 2 < 32) { ISSUE_B(j + 2, (j + 2) % NSTAGE, nbase); cp_commit(); }

            const int tileg = nbase + (j >> 2), c = j & 3;
            if (c == 0) {
#pragma unroll
                for (int mt = 0; mt < 4; mt++)
#pragma unroll
                    for (int nt = 0; nt < 4; nt++)
#pragma unroll
                        for (int q = 0; q < 4; q++) {
                            acc0[mt][nt][q] = 0.0f; acc1[mt][nt][q] = 0.0f;
                        }
            }
#pragma unroll
            for (int k16 = 0; k16 < 4; k16++) {
                const int kloc  = k16 * 16;
                const int kglob = c * KCH + kloc;
                uint32_t ah[4][4], al[4][4], beh[4][2], bel[4][2];

#pragma unroll
                for (int ntp = 0; ntp < 2; ntp++) {
                    const int g   = lane >> 3;
                    const int row = wn * 32 + ntp * 16 + ((g >> 1) << 3) + (lane & 7);
                    const int col = kloc + ((g & 1) << 3);
                    uint32_t r4[4];
                    ldsm4(r4, addrB(sb, stage, 0, row, col));
                    beh[ntp * 2][0] = r4[0]; beh[ntp * 2][1] = r4[1];
                    beh[ntp * 2 + 1][0] = r4[2]; beh[ntp * 2 + 1][1] = r4[3];
                }
#pragma unroll
                for (int mt = 0; mt < 4; mt++) {
                    const int row = wm * 64 + mt * 16 + (lane & 15);
                    const int col = kglob + ((lane >> 4) << 3);
                    ldsm4(ah[mt], addrA(sb, 0, row, col));
                }
#pragma unroll
                for (int mt = 0; mt < 4; mt++)
#pragma unroll
                    for (int nt = 0; nt < 4; nt++)
                        mma16816(acc0[mt][nt], ah[mt], beh[nt]);

#pragma unroll
                for (int ntp = 0; ntp < 2; ntp++) {
                    const int g   = lane >> 3;
                    const int row = wn * 32 + ntp * 16 + ((g >> 1) << 3) + (lane & 7);
                    const int col = kloc + ((g & 1) << 3);
                    uint32_t r4[4];
                    ldsm4(r4, addrB(sb, stage, 1, row, col));
                    bel[ntp * 2][0] = r4[0]; bel[ntp * 2][1] = r4[1];
                    bel[ntp * 2 + 1][0] = r4[2]; bel[ntp * 2 + 1][1] = r4[3];
                }
#pragma unroll
                for (int mt = 0; mt < 4; mt++) {
                    const int row = wm * 64 + mt * 16 + (lane & 15);
                    const int col = kglob + ((lane >> 4) << 3);
                    ldsm4(al[mt], addrA(sb, 1, row, col));
                }
#pragma unroll
                for (int mt = 0; mt < 4; mt++)
#pragma unroll
                    for (int nt = 0; nt < 4; nt++)
                        mma16816(acc1[mt][nt], ah[mt], bel[nt]);
#pragma unroll
                for (int mt = 0; mt < 4; mt++)
#pragma unroll
                    for (int nt = 0; nt < 4; nt++)
                        mma16816(acc1[mt][nt], al[mt], beh[nt]);
            }

            if (c == 3) {
                const int nb = tileg * NTILE + wn * 32 + (lane & 3) * 2;
#pragma unroll
                for (int nt = 0; nt < 4; nt++) {
                    const int n0 = nb + nt * 8;
                    const float bq0 = __ldg(&g_Bsq[n0]);
                    const float bq1 = __ldg(&g_Bsq[n0 + 1]);
#pragma unroll
                    for (int mt = 0; mt < 4; mt++) {
                        const float a00 = acc0[mt][nt][0] + acc1[mt][nt][0] * LO_UNSCALE;
                        const float a01 = acc0[mt][nt][1] + acc1[mt][nt][1] * LO_UNSCALE;
                        const float a10 = acc0[mt][nt][2] + acc1[mt][nt][2] * LO_UNSCALE;
                        const float a11 = acc0[mt][nt][3] + acc1[mt][nt][3] * LO_UNSCALE;
                        const int r0 = mt * 2, r1 = mt * 2 + 1;
                        float d;
                        d = fmaf(-2.0f, a00, av[r0] + bq0);
                        if (d < bestd[r0]) { bestd[r0] = d; besti[r0] = n0; }
                        d = fmaf(-2.0f, a01, av[r0] + bq1);
                        if (d < bestd[r0]) { bestd[r0] = d; besti[r0] = n0 + 1; }
                        d = fmaf(-2.0f, a10, av[r1] + bq0);
                        if (d < bestd[r1]) { bestd[r1] = d; besti[r1] = n0; }
                        d = fmaf(-2.0f, a11, av[r1] + bq1);
                        if (d < bestd[r1]) { bestd[r1] = d; besti[r1] = n0 + 1; }
                    }
                }
            }
        }

        __syncthreads();

#pragma unroll
        for (int k = 0; k < 8; k++) {
#pragma unroll
            for (int off = 1; off <= 2; off <<= 1) {
                float od = __shfl_xor_sync(0xffffffffu, bestd[k], off);
                int   oi = __shfl_xor_sync(0xffffffffu, besti[k], off);
                if (od < bestd[k] || (od == bestd[k] && oi < besti[k])) {
                    bestd[k] = od; besti[k] = oi;
                }
            }
        }
        if ((lane & 3) == 0) {
            const size_t xo = (size_t)((u & 7) * 4 + wn) * MTOK + t0g;
#pragma unroll
            for (int k = 0; k < 8; k++) {
                const int mt = k >> 1, h = k & 1;
                const int row = wm * 64 + mt * 16 + (lane >> 2) + h * 8;
                g_pd[xo + row] = bestd[k];
                g_pi[xo + row] = besti[k];
            }
        }
    }
#undef ISSUE_B
}

// ---------------------------------------------------------------------------
// Merge 32 partials per token (lexicographic == global first-min scan).
__global__ void k_merge(float* __restrict__ out) {
    int m = blockIdx.x * 256 + threadIdx.x;
    float bd = g_pd[m]; int bi = g_pi[m];
#pragma unroll
    for (int x = 1; x < 32; x++) {
        float d2 = g_pd[(size_t)x * MTOK + m];
        int   i2 = g_pi[(size_t)x * MTOK + m];
        if (d2 < bd || (d2 == bd && i2 < bi)) { bd = d2; bi = i2; }
    }
    g_idx[m] = bi;
    out[BDT + 1 + m] = (float)bi;
}

// ---------------------------------------------------------------------------
// Direct gather + STE + loss (R1-form, float4/int4) + ticketed final reduce.
__global__ void __launch_bounds__(256)
k_gather(const float* __restrict__ z,
         const float* __restrict__ emb,
         float* __restrict__ out) {
    __shared__ double red[256];
    __shared__ int is_last;
    const int tid = threadIdx.x;
    const size_t stride = (size_t)GATHER_BLOCKS * 256;

    double ls = 0.0;
    for (size_t v = (size_t)blockIdx.x * 256 + tid; v < (size_t)(BDT / 4); v += stride) {
        const size_t i = v * 4;                  // 4 consecutive t, same (b,d)
        const int t  = (int)(i & 2047);
        const int bd = (int)(i >> 11);
        const int d  = bd & 255, b = bd >> 8;
        const int m0 = (b << 11) + t;
        const int4  cd = *(const int4*)(g_idx + m0);
        const float4 zp = *(const float4*)(z + i);
        float q0 = __ldg(&emb[(size_t)cd.x * DD + d]);
        float q1 = __ldg(&emb[(size_t)cd.y * DD + d]);
        float q2 = __ldg(&emb[(size_t)cd.z * DD + d]);
        float q3 = __ldg(&emb[(size_t)cd.w * DD + d]);
        float d0 = q0 - zp.x, d1 = q1 - zp.y, d2 = q2 - zp.z, d3 = q3 - zp.w;
        float4 o;
        o.x = zp.x + d0; o.y = zp.y + d1; o.z = zp.z + d2; o.w = zp.w + d3;
        *(float4*)(out + i) = o;
        ls += (double)(d0 * d0) + (double)(d1 * d1)
            + (double)(d2 * d2) + (double)(d3 * d3);
    }
    red[tid] = ls;
    __syncthreads();
#pragma unroll
    for (int s = 128; s; s >>= 1) {
        if (tid < s) red[tid] += red[tid + s];
        __syncthreads();
    }
    if (tid == 0) {
        g_part[blockIdx.x] = red[0];
        __threadfence();
        unsigned int tk = atomicAdd(&g_done, 1u);
        is_last = (tk == GATHER_BLOCKS - 1);
    }
    __syncthreads();

    if (is_last) {
        double s = 0.0;
#pragma unroll
        for (int k = 0; k < GATHER_BLOCKS / 256; k++)
            s += g_part[(size_t)k * 256 + tid];
        __syncthreads();
        red[tid] = s;
        __syncthreads();
#pragma unroll
        for (int st = 128; st; st >>= 1) {
            if (tid < st) red[tid] += red[tid + st];
            __syncthreads();
        }
        if (tid == 0) {
            out[BDT] = (float)(1.25 * red[0] / (double)BDT);
            g_done = 0;                  // reset for graph replay
        }
    }
}

// ---------------------------------------------------------------------------
extern "C" void kernel_launch(void* const* d_in, const int* in_sizes, int n_in,
                              void* d_out, int out_size) {
    const float* z   = (const float*)d_in[0];
    const float* emb = (const float*)d_in[1];
    float* out = (float*)d_out;

    cudaFuncSetAttribute(k_mma, cudaFuncAttributeMaxDynamicSharedMemorySize, DYN_SMEM);

    k_prep<<<2048, 256>>>(z, emb);
    k_mma<<<NCTA, 256, DYN_SMEM>>>();
    k_merge<<<MTOK / 256, 256>>>(out);
    k_gather<<<GATHER_BLOCKS, 256>>>(z, emb, out);
}

// round 14
// speedup vs baseline: 1.0787x; 1.0039x over previous
#include <cuda_runtime.h>
#include <cuda_fp16.h>
#include <cstdint>
#include <math_constants.h>

// ---------------------------------------------------------------------------
#define BB   8
#define DD   256
#define TT   2048
#define NE   8192
#define MTOK (BB * TT)        // 16384
#define BDT  (BB * DD * TT)   // 4194304

#define MT    128             // tokens per tile
#define NTILE 128             // codes per N-tile
#define NBLK  8               // n-blocks per token tile (1024 codes each)
#define NUNITS (MTOK / MT * NBLK)   // 1024 work units
#define NCTA  148
#define KCH   64

#define GATHER_BLOCKS 256     // 64 tokens per block
#define LO_SCALE   4096.0f
#define LO_UNSCALE 2.44140625e-4f    // 2^-12

// ---------------------------------------------------------------------------
// NUMERICS NOTE: d-values are degenerate (spread ~2e-3 around ||z||^2~256 vs
// ulp(256)=3e-5) — argmin is decided by first-index tie-break inside the
// lowest fp32 rounding cell. av/bq computed exactly as proven in R10/R13:
// per-64d-slice fp64 partial in g_Ap[y][m], summed in fixed order.
__device__ double g_Ap[4][MTOK];      // ||z||^2 64d-slice partials (fp64)
__device__ float  g_Bsq[NE];
__device__ double g_part[GATHER_BLOCKS];
__device__ unsigned int g_done = 0;   // gather ticket (self-resetting)
__device__ __half g_Zh[(size_t)MTOK * DD];
__device__ __half g_Zl[(size_t)MTOK * DD];
__device__ __half g_Eh[(size_t)NE * DD];
__device__ __half g_El[(size_t)NE * DD];
// partials transposed: [x][m], x = nblk*4 + wn
__device__ float  g_pd[32 * (size_t)MTOK];
__device__ int    g_pi[32 * (size_t)MTOK];

// ---------------------------------------------------------------------------
__device__ __forceinline__ uint32_t smem_u32(const void* p) {
    uint32_t a;
    asm("{ .reg .u64 t; cvta.to.shared.u64 t, %1; cvt.u32.u64 %0, t; }"
        : "=r"(a) : "l"(p));
    return a;
}
__device__ __forceinline__ void cp16(uint32_t dst, const void* src) {
    asm volatile("cp.async.cg.shared.global [%0], [%1], 16;" :: "r"(dst), "l"(src));
}
__device__ __forceinline__ void cp_commit() {
    asm volatile("cp.async.commit_group;" ::: "memory");
}
template <int N>
__device__ __forceinline__ void cp_wait() {
    asm volatile("cp.async.wait_group %0;" :: "n"(N) : "memory");
}
__device__ __forceinline__ void ldsm4(uint32_t* r, uint32_t a) {
    asm volatile("ldmatrix.sync.aligned.m8n8.x4.shared.b16 {%0,%1,%2,%3}, [%4];"
        : "=r"(r[0]), "=r"(r[1]), "=r"(r[2]), "=r"(r[3]) : "r"(a));
}
__device__ __forceinline__ void mma16816(float* d, const uint32_t* a, const uint32_t* b) {
    asm volatile("mma.sync.aligned.m16n8k16.row.col.f32.f16.f16.f32 "
        "{%0,%1,%2,%3}, {%4,%5,%6,%7}, {%8,%9}, {%0,%1,%2,%3};"
        : "+f"(d[0]), "+f"(d[1]), "+f"(d[2]), "+f"(d[3])
        : "r"(a[0]), "r"(a[1]), "r"(a[2]), "r"(a[3]), "r"(b[0]), "r"(b[1]));
}

#define OFF_B   131072
#define NSTAGE  3
#define DYN_SMEM (1024 + OFF_B + NSTAGE * 32768)

// gather dynamic smem: erowT [256][68] floats + codes[64]
#define EROWT_PITCH 68
#define G_SMEM (DD * EROWT_PITCH * 4 + 256)

__device__ __forceinline__ uint32_t addrA(uint32_t sb, int split, int row, int k) {
    return sb + split * 65536 + row * 512 + ((k * 2) ^ ((row & 7) << 4));
}
__device__ __forceinline__ uint32_t addrB(uint32_t sb, int stage, int half, int row, int k) {
    return sb + OFF_B + stage * 32768 + half * 16384 + row * 128
         + ((k * 2) ^ ((row & 7) << 4));
}

// ---------------------------------------------------------------------------
// Fused prep (R13-proven, unchanged).
__global__ void __launch_bounds__(256)
k_prep(const float* __restrict__ z, const float* __restrict__ emb) {
    __shared__ float  tile[64][65];
    __shared__ double sq[4][64];
    const int tid = threadIdx.x;

    if (blockIdx.x < 1024) {
        const int x = blockIdx.x & 31, y = (blockIdx.x >> 5) & 3, b = blockIdx.x >> 7;
        const int d0 = y * 64, t0 = x * 64;
        const int tx = tid & 63, ty = tid >> 6;

        for (int r = ty; r < 64; r += 4)
            tile[r][tx] = z[((size_t)b * DD + d0 + r) * TT + t0 + tx];
        __syncthreads();

        {
            const int tl = tid & 63, q = tid >> 6;
            double s = 0.0;
#pragma unroll
            for (int dl = 0; dl < 16; dl++) {
                float v = tile[q * 16 + dl][tl];
                s += (double)v * v;
            }
            sq[q][tl] = s;
        }
        __syncthreads();
        if (tid < 64) {
            double tot = ((sq[0][tid] + sq[1][tid]) + sq[2][tid]) + sq[3][tid];
            g_Ap[y][b * TT + t0 + tid] = tot;   // THIS y-slice's total only
        }
        {
            const int tx2 = tid & 31, ty2 = tid >> 5;
#pragma unroll
            for (int r = ty2; r < 64; r += 8) {
                size_t m = (size_t)b * TT + t0 + r;
                float v0 = tile[2 * tx2][r], v1 = tile[2 * tx2 + 1][r];
                __half h0 = __float2half(v0), h1 = __float2half(v1);
                __half l0 = __float2half((v0 - __half2float(h0)) * LO_SCALE);
                __half l1 = __float2half((v1 - __half2float(h1)) * LO_SCALE);
                *(__half2*)&g_Zh[m * DD + d0 + 2 * tx2] = __halves2half2(h0, h1);
                *(__half2*)&g_Zl[m * DD + d0 + 2 * tx2] = __halves2half2(l0, l1);
            }
        }
    } else {
        const int row  = (blockIdx.x - 1024) * 8 + (tid >> 5);
        const int lane = tid & 31;
        const float* p = emb + (size_t)row * DD;
        double s = 0.0;
#pragma unroll
        for (int it = 0; it < 4; it++) {
            int d = it * 64 + 2 * lane;
            float2 v = *(const float2*)(p + d);
            __half h0 = __float2half(v.x), h1 = __float2half(v.y);
            __half l0 = __float2half((v.x - __half2float(h0)) * LO_SCALE);
            __half l1 = __float2half((v.y - __half2float(h1)) * LO_SCALE);
            *(__half2*)&g_Eh[(size_t)row * DD + d] = __halves2half2(h0, h1);
            *(__half2*)&g_El[(size_t)row * DD + d] = __halves2half2(l0, l1);
            s += (double)v.x * v.x + (double)v.y * v.y;
        }
#pragma unroll
        for (int off = 16; off; off >>= 1) s += __shfl_down_sync(0xffffffffu, s, off);
        if (lane == 0) g_Bsq[row] = (float)s;
    }
}

// ---------------------------------------------------------------------------
// Persistent GEMM + fused argmin (R13-proven, unchanged).
__global__ void __launch_bounds__(256, 1)
k_mma() {
    extern __shared__ char smem_raw[];
    const uint32_t raw = smem_u32(smem_raw);
    const uint32_t sb  = (raw + 1023) & ~1023u;

    const int tid  = threadIdx.x;
    const int wid  = tid >> 5, lane = tid & 31;
    const int wm   = wid >> 2, wn   = wid & 3;

    const int u0 = (int)(((long long)blockIdx.x * NUNITS) / NCTA);
    const int u1 = (int)(((long long)(blockIdx.x + 1) * NUNITS) / NCTA);

#define ISSUE_B(J, STAGE, NBASE) do {                                         \
    int _tg = (NBASE) + ((J) >> 2), _c = (J) & 3;                             \
    _Pragma("unroll")                                                         \
    for (int _h = 0; _h < 2; _h++) {                                          \
        const __half* _src = (_h ? g_El : g_Eh)                               \
                           + (size_t)(_tg * NTILE) * DD + _c * KCH;           \
        _Pragma("unroll")                                                     \
        for (int _j = 0; _j < 4; _j++) {                                      \
            int _seg = tid + _j * 256;                                        \
            int _row = _seg >> 3, _sg = _seg & 7;                             \
            cp16(addrB(sb, (STAGE), _h, _row, _sg * 8),                       \
                 _src + (size_t)_row * DD + _sg * 8);                         \
        }                                                                     \
    }                                                                         \
} while (0)

    int prev_tile = -1;
    for (int u = u0; u < u1; u++) {
        const int tile0 = u >> 3;
        const int nbase = (u & 7) * 8;
        const int t0g   = tile0 * MT;

        if (tile0 != prev_tile) {
            prev_tile = tile0;
#pragma unroll
            for (int si = 0; si < 2; si++) {
                const __half* src = (si ? g_Zl : g_Zh) + (size_t)t0g * DD;
#pragma unroll
                for (int j = 0; j < 16; j++) {
                    int seg = tid + j * 256;
                    int row = seg >> 5, sg = seg & 31;
                    cp16(sb + si * 65536 + row * 512 + ((sg * 16) ^ ((row & 7) << 4)),
                         src + (size_t)row * DD + sg * 8);
                }
            }
        }
        ISSUE_B(0, 0, nbase);
        cp_commit();
        ISSUE_B(1, 1, nbase);
        cp_commit();

        float av[8];
#pragma unroll
        for (int mt = 0; mt < 4; mt++) {
            int r0 = t0g + wm * 64 + mt * 16 + (lane >> 2);
            av[mt * 2] = (float)(((g_Ap[0][r0] + g_Ap[1][r0])
                                 + g_Ap[2][r0]) + g_Ap[3][r0]);
            av[mt * 2 + 1] = (float)(((g_Ap[0][r0 + 8] + g_Ap[1][r0 + 8])
                                     + g_Ap[2][r0 + 8]) + g_Ap[3][r0 + 8]);
        }
        float bestd[8]; int besti[8];
#pragma unroll
        for (int k = 0; k < 8; k++) { bestd[k] = CUDART_INF_F; besti[k] = 0; }

        float acc0[4][4][4], acc1[4][4][4];

        for (int j = 0; j < 32; j++) {
            const int stage = j % NSTAGE;
            if (j < 31) cp_wait<1>(); else cp_wait<0>();
            __syncthreads();
            if (j + 2 < 32) { ISSUE_B(j + 2, (j + 2) % NSTAGE, nbase); cp_commit(); }

            const int tileg = nbase + (j >> 2), c = j & 3;
            if (c == 0) {
#pragma unroll
                for (int mt = 0; mt < 4; mt++)
#pragma unroll
                    for (int nt = 0; nt < 4; nt++)
#pragma unroll
                        for (int q = 0; q < 4; q++) {
                            acc0[mt][nt][q] = 0.0f; acc1[mt][nt][q] = 0.0f;
                        }
            }
#pragma unroll
            for (int k16 = 0; k16 < 4; k16++) {
                const int kloc  = k16 * 16;
                const int kglob = c * KCH + kloc;
                uint32_t ah[4][4], al[4][4], beh[4][2], bel[4][2];

#pragma unroll
                for (int ntp = 0; ntp < 2; ntp++) {
                    const int g   = lane >> 3;
                    const int row = wn * 32 + ntp * 16 + ((g >> 1) << 3) + (lane & 7);
                    const int col = kloc + ((g & 1) << 3);
                    uint32_t r4[4];
                    ldsm4(r4, addrB(sb, stage, 0, row, col));
                    beh[ntp * 2][0] = r4[0]; beh[ntp * 2][1] = r4[1];
                    beh[ntp * 2 + 1][0] = r4[2]; beh[ntp * 2 + 1][1] = r4[3];
                }
#pragma unroll
                for (int mt = 0; mt < 4; mt++) {
                    const int row = wm * 64 + mt * 16 + (lane & 15);
                    const int col = kglob + ((lane >> 4) << 3);
                    ldsm4(ah[mt], addrA(sb, 0, row, col));
                }
#pragma unroll
                for (int mt = 0; mt < 4; mt++)
#pragma unroll
                    for (int nt = 0; nt < 4; nt++)
                        mma16816(acc0[mt][nt], ah[mt], beh[nt]);

#pragma unroll
                for (int ntp = 0; ntp < 2; ntp++) {
                    const int g   = lane >> 3;
                    const int row = wn * 32 + ntp * 16 + ((g >> 1) << 3) + (lane & 7);
                    const int col = kloc + ((g & 1) << 3);
                    uint32_t r4[4];
                    ldsm4(r4, addrB(sb, stage, 1, row, col));
                    bel[ntp * 2][0] = r4[0]; bel[ntp * 2][1] = r4[1];
                    bel[ntp * 2 + 1][0] = r4[2]; bel[ntp * 2 + 1][1] = r4[3];
                }
#pragma unroll
                for (int mt = 0; mt < 4; mt++) {
                    const int row = wm * 64 + mt * 16 + (lane & 15);
                    const int col = kglob + ((lane >> 4) << 3);
                    ldsm4(al[mt], addrA(sb, 1, row, col));
                }
#pragma unroll
                for (int mt = 0; mt < 4; mt++)
#pragma unroll
                    for (int nt = 0; nt < 4; nt++)
                        mma16816(acc1[mt][nt], ah[mt], bel[nt]);
#pragma unroll
                for (int mt = 0; mt < 4; mt++)
#pragma unroll
                    for (int nt = 0; nt < 4; nt++)
                        mma16816(acc1[mt][nt], al[mt], beh[nt]);
            }

            if (c == 3) {
                const int nb = tileg * NTILE + wn * 32 + (lane & 3) * 2;
#pragma unroll
                for (int nt = 0; nt < 4; nt++) {
                    const int n0 = nb + nt * 8;
                    const float bq0 = __ldg(&g_Bsq[n0]);
                    const float bq1 = __ldg(&g_Bsq[n0 + 1]);
#pragma unroll
                    for (int mt = 0; mt < 4; mt++) {
                        const float a00 = acc0[mt][nt][0] + acc1[mt][nt][0] * LO_UNSCALE;
                        const float a01 = acc0[mt][nt][1] + acc1[mt][nt][1] * LO_UNSCALE;
                        const float a10 = acc0[mt][nt][2] + acc1[mt][nt][2] * LO_UNSCALE;
                        const float a11 = acc0[mt][nt][3] + acc1[mt][nt][3] * LO_UNSCALE;
                        const int r0 = mt * 2, r1 = mt * 2 + 1;
                        float d;
                        d = fmaf(-2.0f, a00, av[r0] + bq0);
                        if (d < bestd[r0]) { bestd[r0] = d; besti[r0] = n0; }
                        d = fmaf(-2.0f, a01, av[r0] + bq1);
                        if (d < bestd[r0]) { bestd[r0] = d; besti[r0] = n0 + 1; }
                        d = fmaf(-2.0f, a10, av[r1] + bq0);
                        if (d < bestd[r1]) { bestd[r1] = d; besti[r1] = n0; }
                        d = fmaf(-2.0f, a11, av[r1] + bq1);
                        if (d < bestd[r1]) { bestd[r1] = d; besti[r1] = n0 + 1; }
                    }
                }
            }
        }

        __syncthreads();

#pragma unroll
        for (int k = 0; k < 8; k++) {
#pragma unroll
            for (int off = 1; off <= 2; off <<= 1) {
                float od = __shfl_xor_sync(0xffffffffu, bestd[k], off);
                int   oi = __shfl_xor_sync(0xffffffffu, besti[k], off);
                if (od < bestd[k] || (od == bestd[k] && oi < besti[k])) {
                    bestd[k] = od; besti[k] = oi;
                }
            }
        }
        if ((lane & 3) == 0) {
            const size_t xo = (size_t)((u & 7) * 4 + wn) * MTOK + t0g;
#pragma unroll
            for (int k = 0; k < 8; k++) {
                const int mt = k >> 1, h = k & 1;
                const int row = wm * 64 + mt * 16 + (lane >> 2) + h * 8;
                g_pd[xo + row] = bestd[k];
                g_pi[xo + row] = besti[k];
            }
        }
    }
#undef ISSUE_B
}

// ---------------------------------------------------------------------------
// Fused merge + gather + STE + loss + ticketed final reduce.
// Block = 64 tokens. emb rows staged TRANSPOSED via float4 LDG (cuts scalar
// LDG count 4x — the measured L1-issue bottleneck), read back via LDS.128.
__global__ void __launch_bounds__(256)
k_gather(const float* __restrict__ z,
         const float* __restrict__ emb,
         float* __restrict__ out) {
    extern __shared__ char gsm[];
    float* erowT = (float*)gsm;                                 // [256][68]
    int*   codes = (int*)(gsm + DD * EROWT_PITCH * 4);          // [64]
    __shared__ double red[256];
    __shared__ int is_last;

    const int tid = threadIdx.x;
    const int m0  = blockIdx.x * 64;
    const int b   = m0 >> 11;
    const int t0  = m0 & 2047;

    // phase A: merge 32 partials per token (lex-min == global first-min scan)
    if (tid < 64) {
        const int m = m0 + tid;
        float bd = g_pd[m]; int bi = g_pi[m];
#pragma unroll
        for (int x = 1; x < 32; x++) {
            float d2 = g_pd[(size_t)x * MTOK + m];
            int   i2 = g_pi[(size_t)x * MTOK + m];
            if (d2 < bd || (d2 == bd && i2 < bi)) { bd = d2; bi = i2; }
        }
        codes[tid] = bi;
        out[BDT + 1 + m] = (float)bi;
    }
    __syncthreads();

    // phase B: stage emb rows transposed: erowT[d][r] = emb[codes[r]][d]
    // float4 LDG (consecutive lanes -> consecutive r: scattered 16B, L2-hit);
    // STS stride-1 in r: conflict-free.
#pragma unroll
    for (int it = 0; it < 16; it++) {
        int idx = it * 256 + tid;          // 0..4095
        int r = idx & 63, c4 = idx >> 6;   // 64 float4-cols per row
        float4 v = *(const float4*)(emb + (size_t)codes[r] * DD + c4 * 4);
        erowT[(c4 * 4 + 0) * EROWT_PITCH + r] = v.x;
        erowT[(c4 * 4 + 1) * EROWT_PITCH + r] = v.y;
        erowT[(c4 * 4 + 2) * EROWT_PITCH + r] = v.z;
        erowT[(c4 * 4 + 3) * EROWT_PITCH + r] = v.w;
    }
    __syncthreads();

    // phase C: coalesced float4 z/out + aligned LDS.128 from erowT
    const float* zb = z   + ((size_t)b * DD) * TT + t0;
    float*       ob = out + ((size_t)b * DD) * TT + t0;
    double ls = 0.0;
#pragma unroll 4
    for (int it = 0; it < 16; it++) {
        int idx = it * 256 + tid;
        int d = idx >> 4, tt0 = (idx & 15) * 4;
        float4 zp = *(const float4*)(zb + (size_t)d * TT + tt0);
        float4 q  = *(const float4*)&erowT[d * EROWT_PITCH + tt0];  // 16B-aligned (68*4=272)
        float d0 = q.x - zp.x, d1 = q.y - zp.y, d2 = q.z - zp.z, d3 = q.w - zp.w;
        float4 o;
        o.x = zp.x + d0; o.y = zp.y + d1; o.z = zp.z + d2; o.w = zp.w + d3;
        *(float4*)(ob + (size_t)d * TT + tt0) = o;
        ls += (double)(d0 * d0) + (double)(d1 * d1)
            + (double)(d2 * d2) + (double)(d3 * d3);
    }
    red[tid] = ls;
    __syncthreads();
#pragma unroll
    for (int s = 128; s; s >>= 1) {
        if (tid < s) red[tid] += red[tid + s];
        __syncthreads();
    }
    if (tid == 0) {
        g_part[blockIdx.x] = red[0];
        __threadfence();
        unsigned int tk = atomicAdd(&g_done, 1u);
        is_last = (tk == GATHER_BLOCKS - 1);
    }
    __syncthreads();

    // last block: deterministic fixed-order reduce of all 256 partials
    if (is_last) {
        double s = g_part[tid];
        __syncthreads();
        red[tid] = s;
        __syncthreads();
#pragma unroll
        for (int st = 128; st; st >>= 1) {
            if (tid < st) red[tid] += red[tid + st];
            __syncthreads();
        }
        if (tid == 0) {
            out[BDT] = (float)(1.25 * red[0] / (double)BDT);
            g_done = 0;                  // reset for graph replay
        }
    }
}

// ---------------------------------------------------------------------------
extern "C" void kernel_launch(void* const* d_in, const int* in_sizes, int n_in,
                              void* d_out, int out_size) {
    const float* z   = (const float*)d_in[0];
    const float* emb = (const float*)d_in[1];
    float* out = (float*)d_out;

    cudaFuncSetAttribute(k_mma, cudaFuncAttributeMaxDynamicSharedMemorySize, DYN_SMEM);
    cudaFuncSetAttribute(k_gather, cudaFuncAttributeMaxDynamicSharedMemorySize, G_SMEM);

    k_prep<<<2048, 256>>>(z, emb);
    k_mma<<<NCTA, 256, DYN_SMEM>>>();
    k_gather<<<GATHER_BLOCKS, 256, G_SMEM>>>(z, emb, out);
}

// round 16
// speedup vs baseline: 1.0788x; 1.0001x over previous
#include <cuda_runtime.h>
#include <cuda_fp16.h>
#include <cstdint>
#include <math_constants.h>

// ---------------------------------------------------------------------------
#define BB   8
#define DD   256
#define TT   2048
#define NE   8192
#define MTOK (BB * TT)        // 16384
#define BDT  (BB * DD * TT)   // 4194304

#define MT    128             // tokens per tile
#define NTILE 128             // codes per N-tile
#define NBLK  8               // n-blocks per token tile (1024 codes each)
#define NUNITS (MTOK / MT * NBLK)   // 1024 work units
#define NCTA  148
#define KCH   64

#define GATHER_BLOCKS 256     // 64 tokens per block
#define LO_SCALE   4096.0f
#define LO_UNSCALE 2.44140625e-4f    // 2^-12

// ---------------------------------------------------------------------------
// NUMERICS NOTE: d-values are degenerate (spread ~2e-3 around ||z||^2~256 vs
// ulp(256)=3e-5) — argmin is decided by first-index tie-break inside the
// lowest fp32 rounding cell. av/bq must be fp64-accumulated then rounded once
// to fp32 (fp64 REGROUPING is safe — proven R9/R13; fp32-level grouping is
// fatal — R11). g_Ap[y][m] holds slice-y's fp64 partial (R12 race fixed).
__device__ double g_Ap[4][MTOK];      // ||z||^2 64d-slice partials (fp64)
__device__ float  g_Bsq[NE];
__device__ double g_part[GATHER_BLOCKS];
__device__ unsigned int g_done = 0;   // gather ticket (self-resetting)
__device__ __half g_Zh[(size_t)MTOK * DD];
__device__ __half g_Zl[(size_t)MTOK * DD];
__device__ __half g_Eh[(size_t)NE * DD];
__device__ __half g_El[(size_t)NE * DD];
// partials transposed: [x][m], x = nblk*4 + wn
__device__ float  g_pd[32 * (size_t)MTOK];
__device__ int    g_pi[32 * (size_t)MTOK];

// ---------------------------------------------------------------------------
__device__ __forceinline__ uint32_t smem_u32(const void* p) {
    uint32_t a;
    asm("{ .reg .u64 t; cvta.to.shared.u64 t, %1; cvt.u32.u64 %0, t; }"
        : "=r"(a) : "l"(p));
    return a;
}
__device__ __forceinline__ void cp16(uint32_t dst, const void* src) {
    asm volatile("cp.async.cg.shared.global [%0], [%1], 16;" :: "r"(dst), "l"(src));
}
__device__ __forceinline__ void cp_commit() {
    asm volatile("cp.async.commit_group;" ::: "memory");
}
template <int N>
__device__ __forceinline__ void cp_wait() {
    asm volatile("cp.async.wait_group %0;" :: "n"(N) : "memory");
}
__device__ __forceinline__ void ldsm4(uint32_t* r, uint32_t a) {
    asm volatile("ldmatrix.sync.aligned.m8n8.x4.shared.b16 {%0,%1,%2,%3}, [%4];"
        : "=r"(r[0]), "=r"(r[1]), "=r"(r[2]), "=r"(r[3]) : "r"(a));
}
__device__ __forceinline__ void mma16816(float* d, const uint32_t* a, const uint32_t* b) {
    asm volatile("mma.sync.aligned.m16n8k16.row.col.f32.f16.f16.f32 "
        "{%0,%1,%2,%3}, {%4,%5,%6,%7}, {%8,%9}, {%0,%1,%2,%3};"
        : "+f"(d[0]), "+f"(d[1]), "+f"(d[2]), "+f"(d[3])
        : "r"(a[0]), "r"(a[1]), "r"(a[2]), "r"(a[3]), "r"(b[0]), "r"(b[1]));
}
__device__ __forceinline__ uint32_t h2u(__half2 h) {
    return *reinterpret_cast<uint32_t*>(&h);
}

#define OFF_B   131072
#define NSTAGE  3
#define DYN_SMEM (1024 + OFF_B + NSTAGE * 32768)

// gather dynamic smem: erowT [256][68] floats + codes[64]
#define EROWT_PITCH 68
#define G_SMEM (DD * EROWT_PITCH * 4 + 256)

__device__ __forceinline__ uint32_t addrA(uint32_t sb, int split, int row, int k) {
    return sb + split * 65536 + row * 512 + ((k * 2) ^ ((row & 7) << 4));
}
__device__ __forceinline__ uint32_t addrB(uint32_t sb, int stage, int half, int row, int k) {
    return sb + OFF_B + stage * 32768 + half * 16384 + row * 128
         + ((k * 2) ^ ((row & 7) << 4));
}

// ---------------------------------------------------------------------------
// Fused prep — R16: float4 loads + interleaved fp64 accumulators (chain-split;
// fp64 regrouping only, fp32 results unchanged).
__global__ void __launch_bounds__(256)
k_prep(const float* __restrict__ z, const float* __restrict__ emb) {
    __shared__ float  tile[64][65];
    __shared__ double sq[4][64];
    const int tid = threadIdx.x;

    if (blockIdx.x < 1024) {
        const int x = blockIdx.x & 31, y = (blockIdx.x >> 5) & 3, b = blockIdx.x >> 7;
        const int d0 = y * 64, t0 = x * 64;

        // float4 tile loads: 1024 float4s, 4 per thread
#pragma unroll
        for (int it = 0; it < 4; it++) {
            int id = it * 256 + tid;
            int row = id >> 4, c4 = (id & 15) * 4;
            float4 v = *(const float4*)(z + ((size_t)b * DD + d0 + row) * TT + t0 + c4);
            tile[row][c4 + 0] = v.x; tile[row][c4 + 1] = v.y;
            tile[row][c4 + 2] = v.z; tile[row][c4 + 3] = v.w;
        }
        __syncthreads();

        // fp64 ssq, 2 interleaved accumulators (chain 16 -> 8 deep)
        {
            const int tl = tid & 63, q = tid >> 6;
            double s0 = 0.0, s1 = 0.0;
#pragma unroll
            for (int dl = 0; dl < 8; dl++) {
                float v0 = tile[q * 16 + 2 * dl][tl];
                float v1 = tile[q * 16 + 2 * dl + 1][tl];
                s0 += (double)v0 * v0;
                s1 += (double)v1 * v1;
            }
            sq[q][tl] = s0 + s1;
        }
        __syncthreads();
        if (tid < 64) {
            double tot = ((sq[0][tid] + sq[1][tid]) + sq[2][tid]) + sq[3][tid];
            g_Ap[y][b * TT + t0 + tid] = tot;   // THIS y-slice's total only
        }
        // half2 split stores
        {
            const int tx2 = tid & 31, ty2 = tid >> 5;
#pragma unroll
            for (int r = ty2; r < 64; r += 8) {
                size_t m = (size_t)b * TT + t0 + r;
                float v0 = tile[2 * tx2][r], v1 = tile[2 * tx2 + 1][r];
                __half h0 = __float2half(v0), h1 = __float2half(v1);
                __half l0 = __float2half((v0 - __half2float(h0)) * LO_SCALE);
                __half l1 = __float2half((v1 - __half2float(h1)) * LO_SCALE);
                *(__half2*)&g_Zh[m * DD + d0 + 2 * tx2] = __halves2half2(h0, h1);
                *(__half2*)&g_Zl[m * DD + d0 + 2 * tx2] = __halves2half2(l0, l1);
            }
        }
    } else {
        // emb role: one warp per code row; float4 loads, 4 fp64 accumulators
        const int row  = (blockIdx.x - 1024) * 8 + (tid >> 5);
        const int lane = tid & 31;
        const float* p = emb + (size_t)row * DD;
        double s0 = 0.0, s1 = 0.0, s2 = 0.0, s3 = 0.0;
#pragma unroll
        for (int it = 0; it < 2; it++) {
            int d = it * 128 + 4 * lane;
            float4 v = *(const float4*)(p + d);
            __half h0 = __float2half(v.x), h1 = __float2half(v.y);
            __half h2 = __float2half(v.z), h3 = __float2half(v.w);
            __half l0 = __float2half((v.x - __half2float(h0)) * LO_SCALE);
            __half l1 = __float2half((v.y - __half2float(h1)) * LO_SCALE);
            __half l2 = __float2half((v.z - __half2float(h2)) * LO_SCALE);
            __half l3 = __float2half((v.w - __half2float(h3)) * LO_SCALE);
            uint2 hp, lp;
            hp.x = h2u(__halves2half2(h0, h1));
            hp.y = h2u(__halves2half2(h2, h3));
            lp.x = h2u(__halves2half2(l0, l1));
            lp.y = h2u(__halves2half2(l2, l3));
            *(uint2*)&g_Eh[(size_t)row * DD + d] = hp;
            *(uint2*)&g_El[(size_t)row * DD + d] = lp;
            s0 += (double)v.x * v.x; s1 += (double)v.y * v.y;
            s2 += (double)v.z * v.z; s3 += (double)v.w * v.w;
        }
        double s = (s0 + s1) + (s2 + s3);
#pragma unroll
        for (int off = 16; off; off >>= 1) s += __shfl_down_sync(0xffffffffu, s, off);
        if (lane == 0) g_Bsq[row] = (float)s;
    }
}

// ---------------------------------------------------------------------------
// Persistent GEMM + fused argmin (R13/R14-proven, unchanged).
__global__ void __launch_bounds__(256, 1)
k_mma() {
    extern __shared__ char smem_raw[];
    const uint32_t raw = smem_u32(smem_raw);
    const uint32_t sb  = (raw + 1023) & ~1023u;

    const int tid  = threadIdx.x;
    const int wid  = tid >> 5, lane = tid & 31;
    const int wm   = wid >> 2, wn   = wid & 3;

    const int u0 = (int)(((long long)blockIdx.x * NUNITS) / NCTA);
    const int u1 = (int)(((long long)(blockIdx.x + 1) * NUNITS) / NCTA);

#define ISSUE_B(J, STAGE, NBASE) do {                                         \
    int _tg = (NBASE) + ((J) >> 2), _c = (J) & 3;                             \
    _Pragma("unroll")                                                         \
    for (int _h = 0; _h < 2; _h++) {                                          \
        const __half* _src = (_h ? g_El : g_Eh)                               \
                           + (size_t)(_tg * NTILE) * DD + _c * KCH;           \
        _Pragma("unroll")                                                     \
        for (int _j = 0; _j < 4; _j++) {                                      \
            int _seg = tid + _j * 256;                                        \
            int _row = _seg >> 3, _sg = _seg & 7;                             \
            cp16(addrB(sb, (STAGE), _h, _row, _sg * 8),                       \
                 _src + (size_t)_row * DD + _sg * 8);                         \
        }                                                                     \
    }                                                                         \
} while (0)

    int prev_tile = -1;
    for (int u = u0; u < u1; u++) {
        const int tile0 = u >> 3;
        const int nbase = (u & 7) * 8;
        const int t0g   = tile0 * MT;

        if (tile0 != prev_tile) {
            prev_tile = tile0;
#pragma unroll
            for (int si = 0; si < 2; si++) {
                const __half* src = (si ? g_Zl : g_Zh) + (size_t)t0g * DD;
#pragma unroll
                for (int j = 0; j < 16; j++) {
                    int seg = tid + j * 256;
                    int row = seg >> 5, sg = seg & 31;
                    cp16(sb + si * 65536 + row * 512 + ((sg * 16) ^ ((row & 7) << 4)),
                         src + (size_t)row * DD + sg * 8);
                }
            }
        }
        ISSUE_B(0, 0, nbase);
        cp_commit();
        ISSUE_B(1, 1, nbase);
        cp_commit();

        float av[8];
#pragma unroll
        for (int mt = 0; mt < 4; mt++) {
            int r0 = t0g + wm * 64 + mt * 16 + (lane >> 2);
            av[mt * 2] = (float)(((g_Ap[0][r0] + g_Ap[1][r0])
                                 + g_Ap[2][r0]) + g_Ap[3][r0]);
            av[mt * 2 + 1] = (float)(((g_Ap[0][r0 + 8] + g_Ap[1][r0 + 8])
                                     + g_Ap[2][r0 + 8]) + g_Ap[3][r0 + 8]);
        }
        float bestd[8]; int besti[8];
#pragma unroll
        for (int k = 0; k < 8; k++) { bestd[k] = CUDART_INF_F; besti[k] = 0; }

        float acc0[4][4][4], acc1[4][4][4];

        for (int j = 0; j < 32; j++) {
            const int stage = j % NSTAGE;
            if (j < 31) cp_wait<1>(); else cp_wait<0>();
            __syncthreads();
            if (j + 2 < 32) { ISSUE_B(j + 2, (j + 2) % NSTAGE, nbase); cp_commit(); }

            const int tileg = nbase + (j >> 2), c = j & 3;
            if (c == 0) {
#pragma unroll
                for (int mt = 0; mt < 4; mt++)
#pragma unroll
                    for (int nt = 0; nt < 4; nt++)
#pragma unroll
                        for (int q = 0; q < 4; q++) {
                            acc0[mt][nt][q] = 0.0f; acc1[mt][nt][q] = 0.0f;
                        }
            }
#pragma unroll
            for (int k16 = 0; k16 < 4; k16++) {
                const int kloc  = k16 * 16;
                const int kglob = c * KCH + kloc;
                uint32_t ah[4][4], al[4][4], beh[4][2], bel[4][2];

#pragma unroll
                for (int ntp = 0; ntp < 2; ntp++) {
                    const int g   = lane >> 3;
                    const int row = wn * 32 + ntp * 16 + ((g >> 1) << 3) + (lane & 7);
                    const int col = kloc + ((g & 1) << 3);
                    uint32_t r4[4];
                    ldsm4(r4, addrB(sb, stage, 0, row, col));
                    beh[ntp * 2][0] = r4[0]; beh[ntp * 2][1] = r4[1];
                    beh[ntp * 2 + 1][0] = r4[2]; beh[ntp * 2 + 1][1] = r4[3];
                }
#pragma unroll
                for (int mt = 0; mt < 4; mt++) {
                    const int row = wm * 64 + mt * 16 + (lane & 15);
                    const int col = kglob + ((lane >> 4) << 3);
                    ldsm4(ah[mt], addrA(sb, 0, row, col));
                }
#pragma unroll
                for (int mt = 0; mt < 4; mt++)
#pragma unroll
                    for (int nt = 0; nt < 4; nt++)
                        mma16816(acc0[mt][nt], ah[mt], beh[nt]);

#pragma unroll
                for (int ntp = 0; ntp < 2; ntp++) {
                    const int g   = lane >> 3;
                    const int row = wn * 32 + ntp * 16 + ((g >> 1) << 3) + (lane & 7);
                    const int col = kloc + ((g & 1) << 3);
                    uint32_t r4[4];
                    ldsm4(r4, addrB(sb, stage, 1, row, col));
                    bel[ntp * 2][0] = r4[0]; bel[ntp * 2][1] = r4[1];
                    bel[ntp * 2 + 1][0] = r4[2]; bel[ntp * 2 + 1][1] = r4[3];
                }
#pragma unroll
                for (int mt = 0; mt < 4; mt++) {
                    const int row = wm * 64 + mt * 16 + (lane & 15);
                    const int col = kglob + ((lane >> 4) << 3);
                    ldsm4(al[mt], addrA(sb, 1, row, col));
                }
#pragma unroll
                for (int mt = 0; mt < 4; mt++)
#pragma unroll
                    for (int nt = 0; nt < 4; nt++)
                        mma16816(acc1[mt][nt], ah[mt], bel[nt]);
#pragma unroll
                for (int mt = 0; mt < 4; mt++)
#pragma unroll
                    for (int nt = 0; nt < 4; nt++)
                        mma16816(acc1[mt][nt], al[mt], beh[nt]);
            }

            if (c == 3) {
                const int nb = tileg * NTILE + wn * 32 + (lane & 3) * 2;
#pragma unroll
                for (int nt = 0; nt < 4; nt++) {
                    const int n0 = nb + nt * 8;
                    const float bq0 = __ldg(&g_Bsq[n0]);
                    const float bq1 = __ldg(&g_Bsq[n0 + 1]);
#pragma unroll
                    for (int mt = 0; mt < 4; mt++) {
                        const float a00 = acc0[mt][nt][0] + acc1[mt][nt][0] * LO_UNSCALE;
                        const float a01 = acc0[mt][nt][1] + acc1[mt][nt][1] * LO_UNSCALE;
                        const float a10 = acc0[mt][nt][2] + acc1[mt][nt][2] * LO_UNSCALE;
                        const float a11 = acc0[mt][nt][3] + acc1[mt][nt][3] * LO_UNSCALE;
                        const int r0 = mt * 2, r1 = mt * 2 + 1;
                        float d;
                        d = fmaf(-2.0f, a00, av[r0] + bq0);
                        if (d < bestd[r0]) { bestd[r0] = d; besti[r0] = n0; }
                        d = fmaf(-2.0f, a01, av[r0] + bq1);
                        if (d < bestd[r0]) { bestd[r0] = d; besti[r0] = n0 + 1; }
                        d = fmaf(-2.0f, a10, av[r1] + bq0);
                        if (d < bestd[r1]) { bestd[r1] = d; besti[r1] = n0; }
                        d = fmaf(-2.0f, a11, av[r1] + bq1);
                        if (d < bestd[r1]) { bestd[r1] = d; besti[r1] = n0 + 1; }
                    }
                }
            }
        }

        __syncthreads();

#pragma unroll
        for (int k = 0; k < 8; k++) {
#pragma unroll
            for (int off = 1; off <= 2; off <<= 1) {
                float od = __shfl_xor_sync(0xffffffffu, bestd[k], off);
                int   oi = __shfl_xor_sync(0xffffffffu, besti[k], off);
                if (od < bestd[k] || (od == bestd[k] && oi < besti[k])) {
                    bestd[k] = od; besti[k] = oi;
                }
            }
        }
        if ((lane & 3) == 0) {
            const size_t xo = (size_t)((u & 7) * 4 + wn) * MTOK + t0g;
#pragma unroll
            for (int k = 0; k < 8; k++) {
                const int mt = k >> 1, h = k & 1;
                const int row = wm * 64 + mt * 16 + (lane >> 2) + h * 8;
                g_pd[xo + row] = bestd[k];
                g_pi[xo + row] = besti[k];
            }
        }
    }
#undef ISSUE_B
}

// ---------------------------------------------------------------------------
// Fused merge + gather + STE + loss + ticketed final reduce (R14-proven).
__global__ void __launch_bounds__(256)
k_gather(const float* __restrict__ z,
         const float* __restrict__ emb,
         float* __restrict__ out) {
    extern __shared__ char gsm[];
    float* erowT = (float*)gsm;                                 // [256][68]
    int*   codes = (int*)(gsm + DD * EROWT_PITCH * 4);          // [64]
    __shared__ double red[256];
    __shared__ int is_last;

    const int tid = threadIdx.x;
    const int m0  = blockIdx.x * 64;
    const int b   = m0 >> 11;
    const int t0  = m0 & 2047;

    if (tid < 64) {
        const int m = m0 + tid;
        float bd = g_pd[m]; int bi = g_pi[m];
#pragma unroll
        for (int x = 1; x < 32; x++) {
            float d2 = g_pd[(size_t)x * MTOK + m];
            int   i2 = g_pi[(size_t)x * MTOK + m];
            if (d2 < bd || (d2 == bd && i2 < bi)) { bd = d2; bi = i2; }
        }
        codes[tid] = bi;
        out[BDT + 1 + m] = (float)bi;
    }
    __syncthreads();

#pragma unroll
    for (int it = 0; it < 16; it++) {
        int idx = it * 256 + tid;
        int r = idx & 63, c4 = idx >> 6;
        float4 v = *(const float4*)(emb + (size_t)codes[r] * DD + c4 * 4);
        erowT[(c4 * 4 + 0) * EROWT_PITCH + r] = v.x;
        erowT[(c4 * 4 + 1) * EROWT_PITCH + r] = v.y;
        erowT[(c4 * 4 + 2) * EROWT_PITCH + r] = v.z;
        erowT[(c4 * 4 + 3) * EROWT_PITCH + r] = v.w;
    }
    __syncthreads();

    const float* zb = z   + ((size_t)b * DD) * TT + t0;
    float*       ob = out + ((size_t)b * DD) * TT + t0;
    double ls = 0.0;
#pragma unroll 4
    for (int it = 0; it < 16; it++) {
        int idx = it * 256 + tid;
        int d = idx >> 4, tt0 = (idx & 15) * 4;
        float4 zp = *(const float4*)(zb + (size_t)d * TT + tt0);
        float4 q  = *(const float4*)&erowT[d * EROWT_PITCH + tt0];
        float d0 = q.x - zp.x, d1 = q.y - zp.y, d2 = q.z - zp.z, d3 = q.w - zp.w;
        float4 o;
        o.x = zp.x + d0; o.y = zp.y + d1; o.z = zp.z + d2; o.w = zp.w + d3;
        *(float4*)(ob + (size_t)d * TT + tt0) = o;
        ls += (double)(d0 * d0) + (double)(d1 * d1)
            + (double)(d2 * d2) + (double)(d3 * d3);
    }
    red[tid] = ls;
    __syncthreads();
#pragma unroll
    for (int s = 128; s; s >>= 1) {
        if (tid < s) red[tid] += red[tid + s];
        __syncthreads();
    }
    if (tid == 0) {
        g_part[blockIdx.x] = red[0];
        __threadfence();
        unsigned int tk = atomicAdd(&g_done, 1u);
        is_last = (tk == GATHER_BLOCKS - 1);
    }
    __syncthreads();

    if (is_last) {
        double s = g_part[tid];
        __syncthreads();
        red[tid] = s;
        __syncthreads();
#pragma unroll
        for (int st = 128; st; st >>= 1) {
            if (tid < st) red[tid] += red[tid + st];
            __syncthreads();
        }
        if (tid == 0) {
            out[BDT] = (float)(1.25 * red[0] / (double)BDT);
            g_done = 0;
        }
    }
}

// ---------------------------------------------------------------------------
extern "C" void kernel_launch(void* const* d_in, const int* in_sizes, int n_in,
                              void* d_out, int out_size) {
    const float* z   = (const float*)d_in[0];
    const float* emb = (const float*)d_in[1];
    float* out = (float*)d_out;

    cudaFuncSetAttribute(k_mma, cudaFuncAttributeMaxDynamicSharedMemorySize, DYN_SMEM);
    cudaFuncSetAttribute(k_gather, cudaFuncAttributeMaxDynamicSharedMemorySize, G_SMEM);

    k_prep<<<2048, 256>>>(z, emb);
    k_mma<<<NCTA, 256, DYN_SMEM>>>();
    k_gather<<<GATHER_BLOCKS, 256, G_SMEM>>>(z, emb, out);
}

// round 17
// speedup vs baseline: 1.0825x; 1.0034x over previous
#include <cuda_runtime.h>
#include <cuda_fp16.h>
#include <cstdint>
#include <math_constants.h>

// ---------------------------------------------------------------------------
#define BB   8
#define DD   256
#define TT   2048
#define NE   8192
#define MTOK (BB * TT)        // 16384
#define BDT  (BB * DD * TT)   // 4194304

#define MT    128             // tokens per tile
#define NTILE 128             // codes per N-tile
#define NBLK  8               // n-blocks per token tile (1024 codes each)
#define NUNITS (MTOK / MT * NBLK)   // 1024 work units
#define NCTA  148
#define KCH   64

#define GATHER_BLOCKS 256     // 64 tokens per block
#define LO_SCALE   4096.0f
#define LO_UNSCALE 2.44140625e-4f    // 2^-12

// ---------------------------------------------------------------------------
// NUMERICS NOTE: d-values are degenerate (spread ~2e-3 around ||z||^2~256 vs
// ulp(256)=3e-5) — argmin is decided by first-index tie-break inside the
// lowest fp32 rounding cell. av/bq must be fp64-accumulated then rounded once
// to fp32 (fp64 REGROUPING is safe — proven R9/R13/R16; fp32-level grouping
// is fatal — R11). g_Ap[y][m] holds slice-y's fp64 partial (R12 race fixed).
__device__ double g_Ap[4][MTOK];      // ||z||^2 64d-slice partials (fp64)
__device__ float  g_Bsq[NE];
__device__ double g_part[GATHER_BLOCKS];
__device__ unsigned int g_done = 0;   // gather ticket (self-resetting)
__device__ __half g_Zh[(size_t)MTOK * DD];
__device__ __half g_Zl[(size_t)MTOK * DD];
__device__ __half g_Eh[(size_t)NE * DD];
__device__ __half g_El[(size_t)NE * DD];
// partials transposed: [x][m], x = nblk*4 + wn
__device__ float  g_pd[32 * (size_t)MTOK];
__device__ int    g_pi[32 * (size_t)MTOK];

// ---------------------------------------------------------------------------
__device__ __forceinline__ uint32_t smem_u32(const void* p) {
    uint32_t a;
    asm("{ .reg .u64 t; cvta.to.shared.u64 t, %1; cvt.u32.u64 %0, t; }"
        : "=r"(a) : "l"(p));
    return a;
}
__device__ __forceinline__ void cp16(uint32_t dst, const void* src) {
    asm volatile("cp.async.cg.shared.global [%0], [%1], 16;" :: "r"(dst), "l"(src));
}
__device__ __forceinline__ void cp_commit() {
    asm volatile("cp.async.commit_group;" ::: "memory");
}
template <int N>
__device__ __forceinline__ void cp_wait() {
    asm volatile("cp.async.wait_group %0;" :: "n"(N) : "memory");
}
__device__ __forceinline__ void ldsm4(uint32_t* r, uint32_t a) {
    asm volatile("ldmatrix.sync.aligned.m8n8.x4.shared.b16 {%0,%1,%2,%3}, [%4];"
        : "=r"(r[0]), "=r"(r[1]), "=r"(r[2]), "=r"(r[3]) : "r"(a));
}
__device__ __forceinline__ void mma16816(float* d, const uint32_t* a, const uint32_t* b) {
    asm volatile("mma.sync.aligned.m16n8k16.row.col.f32.f16.f16.f32 "
        "{%0,%1,%2,%3}, {%4,%5,%6,%7}, {%8,%9}, {%0,%1,%2,%3};"
        : "+f"(d[0]), "+f"(d[1]), "+f"(d[2]), "+f"(d[3])
        : "r"(a[0]), "r"(a[1]), "r"(a[2]), "r"(a[3]), "r"(b[0]), "r"(b[1]));
}
__device__ __forceinline__ uint32_t h2u(__half2 h) {
    return *reinterpret_cast<uint32_t*>(&h);
}

#define OFF_B   131072
#define NSTAGE  3
#define DYN_SMEM (1024 + OFF_B + NSTAGE * 32768)

// gather dynamic smem: erowT [256][68] floats + codes[64]
#define EROWT_PITCH 68
#define G_SMEM (DD * EROWT_PITCH * 4 + 256)

__device__ __forceinline__ uint32_t addrA(uint32_t sb, int split, int row, int k) {
    return sb + split * 65536 + row * 512 + ((k * 2) ^ ((row & 7) << 4));
}
__device__ __forceinline__ uint32_t addrB(uint32_t sb, int stage, int half, int row, int k) {
    return sb + OFF_B + stage * 32768 + half * 16384 + row * 128
         + ((k * 2) ^ ((row & 7) << 4));
}

// pack 8 consecutive floats (already in registers) into hi/lo uint4 splits
__device__ __forceinline__ void pack8(const float* v, uint4& hv, uint4& lv) {
    uint32_t* hw = (uint32_t*)&hv;
    uint32_t* lw = (uint32_t*)&lv;
#pragma unroll
    for (int j = 0; j < 4; j++) {
        float v0 = v[2 * j], v1 = v[2 * j + 1];
        __half h0 = __float2half(v0), h1 = __float2half(v1);
        __half l0 = __float2half((v0 - __half2float(h0)) * LO_SCALE);
        __half l1 = __float2half((v1 - __half2float(h1)) * LO_SCALE);
        hw[j] = h2u(__halves2half2(h0, h1));
        lw[j] = h2u(__halves2half2(l0, l1));
    }
}

// ---------------------------------------------------------------------------
// Fused prep — R17: STG.128 split stores (store-issue was the measured limit).
__global__ void __launch_bounds__(256)
k_prep(const float* __restrict__ z, const float* __restrict__ emb) {
    __shared__ float  tile[64][65];
    __shared__ double sq[4][64];
    const int tid = threadIdx.x;

    if (blockIdx.x < 1024) {
        const int x = blockIdx.x & 31, y = (blockIdx.x >> 5) & 3, b = blockIdx.x >> 7;
        const int d0 = y * 64, t0 = x * 64;

        // float4 tile loads: 1024 float4s, 4 per thread
#pragma unroll
        for (int it = 0; it < 4; it++) {
            int id = it * 256 + tid;
            int row = id >> 4, c4 = (id & 15) * 4;
            float4 v = *(const float4*)(z + ((size_t)b * DD + d0 + row) * TT + t0 + c4);
            tile[row][c4 + 0] = v.x; tile[row][c4 + 1] = v.y;
            tile[row][c4 + 2] = v.z; tile[row][c4 + 3] = v.w;
        }
        __syncthreads();

        // fp64 ssq, 2 interleaved accumulators (R16-proven)
        {
            const int tl = tid & 63, q = tid >> 6;
            double s0 = 0.0, s1 = 0.0;
#pragma unroll
            for (int dl = 0; dl < 8; dl++) {
                float v0 = tile[q * 16 + 2 * dl][tl];
                float v1 = tile[q * 16 + 2 * dl + 1][tl];
                s0 += (double)v0 * v0;
                s1 += (double)v1 * v1;
            }
            sq[q][tl] = s0 + s1;
        }
        __syncthreads();
        if (tid < 64) {
            double tot = ((sq[0][tid] + sq[1][tid]) + sq[2][tid]) + sq[3][tid];
            g_Ap[y][b * TT + t0 + tid] = tot;   // THIS y-slice's total only
        }

        // splits: 512 (row, 8d-group) pairs, 2 per thread; uint4 stores.
        // p = pp*256 + tid -> warp covers 4 full rows (contiguous 128B runs).
#pragma unroll
        for (int pp = 0; pp < 2; pp++) {
            const int p = pp * 256 + tid;
            const int r = p >> 3, g = p & 7;   // token row, d-group
            float v[8];
#pragma unroll
            for (int j = 0; j < 8; j++) v[j] = tile[8 * g + j][r];
            uint4 hv, lv;
            pack8(v, hv, lv);
            const size_t m = (size_t)b * TT + t0 + r;
            *(uint4*)&g_Zh[m * DD + d0 + 8 * g] = hv;
            *(uint4*)&g_Zl[m * DD + d0 + 8 * g] = lv;
        }
    } else {
        // emb role: one warp per code row; lane owns 8 consecutive d.
        const int row  = (blockIdx.x - 1024) * 8 + (tid >> 5);
        const int lane = tid & 31;
        const float* p = emb + (size_t)row * DD;
        const int d = 8 * lane;
        float v[8];
        *(float4*)&v[0] = *(const float4*)(p + d);
        *(float4*)&v[4] = *(const float4*)(p + d + 4);
        uint4 hv, lv;
        pack8(v, hv, lv);
        *(uint4*)&g_Eh[(size_t)row * DD + d] = hv;
        *(uint4*)&g_El[(size_t)row * DD + d] = lv;
        // fp64 ssq over this lane's 8 d's (2 interleaved accs), then warp-reduce
        double s0 = 0.0, s1 = 0.0;
#pragma unroll
        for (int j = 0; j < 4; j++) {
            s0 += (double)v[2 * j] * v[2 * j];
            s1 += (double)v[2 * j + 1] * v[2 * j + 1];
        }
        double s = s0 + s1;
#pragma unroll
        for (int off = 16; off; off >>= 1) s += __shfl_down_sync(0xffffffffu, s, off);
        if (lane == 0) g_Bsq[row] = (float)s;
    }
}

// ---------------------------------------------------------------------------
// Persistent GEMM + fused argmin (R13/R14-proven, unchanged).
__global__ void __launch_bounds__(256, 1)
k_mma() {
    extern __shared__ char smem_raw[];
    const uint32_t raw = smem_u32(smem_raw);
    const uint32_t sb  = (raw + 1023) & ~1023u;

    const int tid  = threadIdx.x;
    const int wid  = tid >> 5, lane = tid & 31;
    const int wm   = wid >> 2, wn   = wid & 3;

    const int u0 = (int)(((long long)blockIdx.x * NUNITS) / NCTA);
    const int u1 = (int)(((long long)(blockIdx.x + 1) * NUNITS) / NCTA);

#define ISSUE_B(J, STAGE, NBASE) do {                                         \
    int _tg = (NBASE) + ((J) >> 2), _c = (J) & 3;                             \
    _Pragma("unroll")                                                         \
    for (int _h = 0; _h < 2; _h++) {                                          \
        const __half* _src = (_h ? g_El : g_Eh)                               \
                           + (size_t)(_tg * NTILE) * DD + _c * KCH;           \
        _Pragma("unroll")                                                     \
        for (int _j = 0; _j < 4; _j++) {                                      \
            int _seg = tid + _j * 256;                                        \
            int _row = _seg >> 3, _sg = _seg & 7;                             \
            cp16(addrB(sb, (STAGE), _h, _row, _sg * 8),                       \
                 _src + (size_t)_row * DD + _sg * 8);                         \
        }                                                                     \
    }                                                                         \
} while (0)

    int prev_tile = -1;
    for (int u = u0; u < u1; u++) {
        const int tile0 = u >> 3;
        const int nbase = (u & 7) * 8;
        const int t0g   = tile0 * MT;

        if (tile0 != prev_tile) {
            prev_tile = tile0;
#pragma unroll
            for (int si = 0; si < 2; si++) {
                const __half* src = (si ? g_Zl : g_Zh) + (size_t)t0g * DD;
#pragma unroll
                for (int j = 0; j < 16; j++) {
                    int seg = tid + j * 256;
                    int row = seg >> 5, sg = seg & 31;
                    cp16(sb + si * 65536 + row * 512 + ((sg * 16) ^ ((row & 7) << 4)),
                         src + (size_t)row * DD + sg * 8);
                }
            }
        }
        ISSUE_B(0, 0, nbase);
        cp_commit();
        ISSUE_B(1, 1, nbase);
        cp_commit();

        float av[8];
#pragma unroll
        for (int mt = 0; mt < 4; mt++) {
            int r0 = t0g + wm * 64 + mt * 16 + (lane >> 2);
            av[mt * 2] = (float)(((g_Ap[0][r0] + g_Ap[1][r0])
                                 + g_Ap[2][r0]) + g_Ap[3][r0]);
            av[mt * 2 + 1] = (float)(((g_Ap[0][r0 + 8] + g_Ap[1][r0 + 8])
                                     + g_Ap[2][r0 + 8]) + g_Ap[3][r0 + 8]);
        }
        float bestd[8]; int besti[8];
#pragma unroll
        for (int k = 0; k < 8; k++) { bestd[k] = CUDART_INF_F; besti[k] = 0; }

        float acc0[4][4][4], acc1[4][4][4];

        for (int j = 0; j < 32; j++) {
            const int stage = j % NSTAGE;
            if (j < 31) cp_wait<1>(); else cp_wait<0>();
            __syncthreads();
            if (j + 2 < 32) { ISSUE_B(j + 2, (j + 2) % NSTAGE, nbase); cp_commit(); }

            const int tileg = nbase + (j >> 2), c = j & 3;
            if (c == 0) {
#pragma unroll
                for (int mt = 0; mt < 4; mt++)
#pragma unroll
                    for (int nt = 0; nt < 4; nt++)
#pragma unroll
                        for (int q = 0; q < 4; q++) {
                            acc0[mt][nt][q] = 0.0f; acc1[mt][nt][q] = 0.0f;
                        }
            }
#pragma unroll
            for (int k16 = 0; k16 < 4; k16++) {
                const int kloc  = k16 * 16;
                const int kglob = c * KCH + kloc;
                uint32_t ah[4][4], al[4][4], beh[4][2], bel[4][2];

#pragma unroll
                for (int ntp = 0; ntp < 2; ntp++) {
                    const int g   = lane >> 3;
                    const int row = wn * 32 + ntp * 16 + ((g >> 1) << 3) + (lane & 7);
                    const int col = kloc + ((g & 1) << 3);
                    uint32_t r4[4];
                    ldsm4(r4, addrB(sb, stage, 0, row, col));
                    beh[ntp * 2][0] = r4[0]; beh[ntp * 2][1] = r4[1];
                    beh[ntp * 2 + 1][0] = r4[2]; beh[ntp * 2 + 1][1] = r4[3];
                }
#pragma unroll
                for (int mt = 0; mt < 4; mt++) {
                    const int row = wm * 64 + mt * 16 + (lane & 15);
                    const int col = kglob + ((lane >> 4) << 3);
                    ldsm4(ah[mt], addrA(sb, 0, row, col));
                }
#pragma unroll
                for (int mt = 0; mt < 4; mt++)
#pragma unroll
                    for (int nt = 0; nt < 4; nt++)
                        mma16816(acc0[mt][nt], ah[mt], beh[nt]);

#pragma unroll
                for (int ntp = 0; ntp < 2; ntp++) {
                    const int g   = lane >> 3;
                    const int row = wn * 32 + ntp * 16 + ((g >> 1) << 3) + (lane & 7);
                    const int col = kloc + ((g & 1) << 3);
                    uint32_t r4[4];
                    ldsm4(r4, addrB(sb, stage, 1, row, col));
                    bel[ntp * 2][0] = r4[0]; bel[ntp * 2][1] = r4[1];
                    bel[ntp * 2 + 1][0] = r4[2]; bel[ntp * 2 + 1][1] = r4[3];
                }
#pragma unroll
                for (int mt = 0; mt < 4; mt++) {
                    const int row = wm * 64 + mt * 16 + (lane & 15);
                    const int col = kglob + ((lane >> 4) << 3);
                    ldsm4(al[mt], addrA(sb, 1, row, col));
                }
#pragma unroll
                for (int mt = 0; mt < 4; mt++)
#pragma unroll
                    for (int nt = 0; nt < 4; nt++)
                        mma16816(acc1[mt][nt], ah[mt], bel[nt]);
#pragma unroll
                for (int mt = 0; mt < 4; mt++)
#pragma unroll
                    for (int nt = 0; nt < 4; nt++)
                        mma16816(acc1[mt][nt], al[mt], beh[nt]);
            }

            if (c == 3) {
                const int nb = tileg * NTILE + wn * 32 + (lane & 3) * 2;
#pragma unroll
                for (int nt = 0; nt < 4; nt++) {
                    const int n0 = nb + nt * 8;
                    const float bq0 = __ldg(&g_Bsq[n0]);
                    const float bq1 = __ldg(&g_Bsq[n0 + 1]);
#pragma unroll
                    for (int mt = 0; mt < 4; mt++) {
                        const float a00 = acc0[mt][nt][0] + acc1[mt][nt][0] * LO_UNSCALE;
                        const float a01 = acc0[mt][nt][1] + acc1[mt][nt][1] * LO_UNSCALE;
                        const float a10 = acc0[mt][nt][2] + acc1[mt][nt][2] * LO_UNSCALE;
                        const float a11 = acc0[mt][nt][3] + acc1[mt][nt][3] * LO_UNSCALE;
                        const int r0 = mt * 2, r1 = mt * 2 + 1;
                        float d;
                        d = fmaf(-2.0f, a00, av[r0] + bq0);
                        if (d < bestd[r0]) { bestd[r0] = d; besti[r0] = n0; }
                        d = fmaf(-2.0f, a01, av[r0] + bq1);
                        if (d < bestd[r0]) { bestd[r0] = d; besti[r0] = n0 + 1; }
                        d = fmaf(-2.0f, a10, av[r1] + bq0);
                        if (d < bestd[r1]) { bestd[r1] = d; besti[r1] = n0; }
                        d = fmaf(-2.0f, a11, av[r1] + bq1);
                        if (d < bestd[r1]) { bestd[r1] = d; besti[r1] = n0 + 1; }
                    }
                }
            }
        }

        __syncthreads();

#pragma unroll
        for (int k = 0; k < 8; k++) {
#pragma unroll
            for (int off = 1; off <= 2; off <<= 1) {
                float od = __shfl_xor_sync(0xffffffffu, bestd[k], off);
                int   oi = __shfl_xor_sync(0xffffffffu, besti[k], off);
                if (od < bestd[k] || (od == bestd[k] && oi < besti[k])) {
                    bestd[k] = od; besti[k] = oi;
                }
            }
        }
        if ((lane & 3) == 0) {
            const size_t xo = (size_t)((u & 7) * 4 + wn) * MTOK + t0g;
#pragma unroll
            for (int k = 0; k < 8; k++) {
                const int mt = k >> 1, h = k & 1;
                const int row = wm * 64 + mt * 16 + (lane >> 2) + h * 8;
                g_pd[xo + row] = bestd[k];
                g_pi[xo + row] = besti[k];
            }
        }
    }
#undef ISSUE_B
}

// ---------------------------------------------------------------------------
// Fused merge + gather + STE + loss + ticketed final reduce (R14-proven).
__global__ void __launch_bounds__(256)
k_gather(const float* __restrict__ z,
         const float* __restrict__ emb,
         float* __restrict__ out) {
    extern __shared__ char gsm[];
    float* erowT = (float*)gsm;                                 // [256][68]
    int*   codes = (int*)(gsm + DD * EROWT_PITCH * 4);          // [64]
    __shared__ double red[256];
    __shared__ int is_last;

    const int tid = threadIdx.x;
    const int m0  = blockIdx.x * 64;
    const int b   = m0 >> 11;
    const int t0  = m0 & 2047;

    if (tid < 64) {
        const int m = m0 + tid;
        float bd = g_pd[m]; int bi = g_pi[m];
#pragma unroll
        for (int x = 1; x < 32; x++) {
            float d2 = g_pd[(size_t)x * MTOK + m];
            int   i2 = g_pi[(size_t)x * MTOK + m];
            if (d2 < bd || (d2 == bd && i2 < bi)) { bd = d2; bi = i2; }
        }
        codes[tid] = bi;
        out[BDT + 1 + m] = (float)bi;
    }
    __syncthreads();

#pragma unroll
    for (int it = 0; it < 16; it++) {
        int idx = it * 256 + tid;
        int r = idx & 63, c4 = idx >> 6;
        float4 v = *(const float4*)(emb + (size_t)codes[r] * DD + c4 * 4);
        erowT[(c4 * 4 + 0) * EROWT_PITCH + r] = v.x;
        erowT[(c4 * 4 + 1) * EROWT_PITCH + r] = v.y;
        erowT[(c4 * 4 + 2) * EROWT_PITCH + r] = v.z;
        erowT[(c4 * 4 + 3) * EROWT_PITCH + r] = v.w;
    }
    __syncthreads();

    const float* zb = z   + ((size_t)b * DD) * TT + t0;
    float*       ob = out + ((size_t)b * DD) * TT + t0;
    double ls = 0.0;
#pragma unroll 4
    for (int it = 0; it < 16; it++) {
        int idx = it * 256 + tid;
        int d = idx >> 4, tt0 = (idx & 15) * 4;
        float4 zp = *(const float4*)(zb + (size_t)d * TT + tt0);
        float4 q  = *(const float4*)&erowT[d * EROWT_PITCH + tt0];
        float d0 = q.x - zp.x, d1 = q.y - zp.y, d2 = q.z - zp.z, d3 = q.w - zp.w;
        float4 o;
        o.x = zp.x + d0; o.y = zp.y + d1; o.z = zp.z + d2; o.w = zp.w + d3;
        *(float4*)(ob + (size_t)d * TT + tt0) = o;
        ls += (double)(d0 * d0) + (double)(d1 * d1)
            + (double)(d2 * d2) + (double)(d3 * d3);
    }
    red[tid] = ls;
    __syncthreads();
#pragma unroll
    for (int s = 128; s; s >>= 1) {
        if (tid < s) red[tid] += red[tid + s];
        __syncthreads();
    }
    if (tid == 0) {
        g_part[blockIdx.x] = red[0];
        __threadfence();
        unsigned int tk = atomicAdd(&g_done, 1u);
        is_last = (tk == GATHER_BLOCKS - 1);
    }
    __syncthreads();

    if (is_last) {
        double s = g_part[tid];
        __syncthreads();
        red[tid] = s;
        __syncthreads();
#pragma unroll
        for (int st = 128; st; st >>= 1) {
            if (tid < st) red[tid] += red[tid + st];
            __syncthreads();
        }
        if (tid == 0) {
            out[BDT] = (float)(1.25 * red[0] / (double)BDT);
            g_done = 0;
        }
    }
}

// ---------------------------------------------------------------------------
extern "C" void kernel_launch(void* const* d_in, const int* in_sizes, int n_in,
                              void* d_out, int out_size) {
    const float* z   = (const float*)d_in[0];
    const float* emb = (const float*)d_in[1];
    float* out = (float*)d_out;

    cudaFuncSetAttribute(k_mma, cudaFuncAttributeMaxDynamicSharedMemorySize, DYN_SMEM);
    cudaFuncSetAttribute(k_gather, cudaFuncAttributeMaxDynamicSharedMemorySize, G_SMEM);

    k_prep<<<2048, 256>>>(z, emb);
    k_mma<<<NCTA, 256, DYN_SMEM>>>();
    k_gather<<<GATHER_BLOCKS, 256, G_SMEM>>>(z, emb, out);
}